// round 1
// baseline (speedup 1.0000x reference)
#include <cuda_runtime.h>
#include <cstdint>

#define Bn  64
#define Ssz 512
#define Dsz 512
#define Hsz 512
#define Gsz 2048   // 4*H

#define NBLK 128   // persistent blocks, 1 per SM (<=148)

// Scratch: xg[s][b][g]  (256 MiB), double-buffered h[j][b], barrier counter
__device__ float    g_xg[(size_t)Ssz * Bn * Gsz];
__device__ float    g_h[2][Hsz * Bn];
__device__ unsigned g_count;

// ---------------------------------------------------------------------------
// reset barrier counter each launch (graph-replay determinism)
// ---------------------------------------------------------------------------
__global__ void reset_kernel() { g_count = 0u; }

// ---------------------------------------------------------------------------
// Phase 1: xg[s][b][n] = dot(inputs[b,s,:], W_ih[n,:]) + b_ih[n] + b_hh[n]
// inputs[b,0]=emb[b], inputs[b,s]=x[b,s-1]  -> row m=b*S+s reads x+(m-1)*D
// GEMM M=32768, N=2048, K=512.  BM=128, BN=64, BK=16, 256 thr, 8x4 micro.
// ---------------------------------------------------------------------------
#define BM 128
#define BN 64
#define BK 16

__global__ __launch_bounds__(256) void xg_gemm(
    const float* __restrict__ x, const float* __restrict__ emb,
    const float* __restrict__ W_ih,
    const float* __restrict__ b_ih, const float* __restrict__ b_hh)
{
    __shared__ float As[BK][BM];
    __shared__ float Bs[BK][BN];

    const int tid = threadIdx.x;
    const int m0 = blockIdx.y * BM;
    const int n0 = blockIdx.x * BN;
    const int tx = tid & 15;     // 0..15 -> 4 n each
    const int ty = tid >> 4;     // 0..15 -> 8 m each

    float acc[8][4];
#pragma unroll
    for (int i = 0; i < 8; i++)
#pragma unroll
        for (int q = 0; q < 4; q++) acc[i][q] = 0.f;

    for (int kk = 0; kk < Dsz; kk += BK) {
        // load A tile: 128 rows x 16 k = 512 float4
#pragma unroll
        for (int i = 0; i < 2; i++) {
            int idx = i * 256 + tid;
            int r   = idx >> 2;      // row 0..127
            int kc  = idx & 3;       // float4 slot in chunk
            int m   = m0 + r;
            int s   = m & (Ssz - 1);
            const float* arow = (s == 0) ? (emb + (size_t)(m >> 9) * Dsz)
                                         : (x   + (size_t)(m - 1) * Dsz);
            float4 v = *(const float4*)(arow + kk + kc * 4);
            As[kc * 4 + 0][r] = v.x;
            As[kc * 4 + 1][r] = v.y;
            As[kc * 4 + 2][r] = v.z;
            As[kc * 4 + 3][r] = v.w;
        }
        // load B tile: 64 rows x 16 k = 256 float4
        {
            int r  = tid >> 2;       // 0..63
            int kc = tid & 3;
            float4 v = *(const float4*)(W_ih + (size_t)(n0 + r) * Dsz + kk + kc * 4);
            Bs[kc * 4 + 0][r] = v.x;
            Bs[kc * 4 + 1][r] = v.y;
            Bs[kc * 4 + 2][r] = v.z;
            Bs[kc * 4 + 3][r] = v.w;
        }
        __syncthreads();

#pragma unroll
        for (int k = 0; k < BK; k++) {
            float4 a0 = *(const float4*)&As[k][ty * 8];
            float4 a1 = *(const float4*)&As[k][ty * 8 + 4];
            float4 bv = *(const float4*)&Bs[k][tx * 4];
            float a[8] = {a0.x, a0.y, a0.z, a0.w, a1.x, a1.y, a1.z, a1.w};
            float b[4] = {bv.x, bv.y, bv.z, bv.w};
#pragma unroll
            for (int i = 0; i < 8; i++)
#pragma unroll
                for (int q = 0; q < 4; q++)
                    acc[i][q] = fmaf(a[i], b[q], acc[i][q]);
        }
        __syncthreads();
    }

    float bias[4];
#pragma unroll
    for (int q = 0; q < 4; q++) {
        int n = n0 + tx * 4 + q;
        bias[q] = b_ih[n] + b_hh[n];
    }
#pragma unroll
    for (int i = 0; i < 8; i++) {
        int m = m0 + ty * 8 + i;
        int b = m >> 9;           // /S
        int s = m & 511;
        float4 v;
        v.x = acc[i][0] + bias[0];
        v.y = acc[i][1] + bias[1];
        v.z = acc[i][2] + bias[2];
        v.w = acc[i][3] + bias[3];
        *(float4*)(g_xg + ((size_t)s * Bn + b) * Gsz + n0 + tx * 4) = v;
    }
}

// ---------------------------------------------------------------------------
// grid-wide software barrier (all NBLK blocks co-resident: 1 block/SM)
// ---------------------------------------------------------------------------
__device__ __forceinline__ void grid_bar(unsigned target)
{
    __threadfence();               // release: h writes visible (gpu scope)
    __syncthreads();
    if (threadIdx.x == 0) {
        atomicAdd(&g_count, 1u);
        volatile unsigned* p = &g_count;
        while (*p < target) { }
        __threadfence();           // acquire
    }
    __syncthreads();
}

// ---------------------------------------------------------------------------
// Phase 2: persistent recurrent kernel.
// 128 blocks x 256 threads. Block owns 4 j-columns (16 gate rows of W_hh,
// cached in smem for all 512 steps). Per step: load h (128KB) to smem,
// 64x16x512 dot, elementwise cell (c in registers), write h ping-pong.
// ---------------------------------------------------------------------------
#define SMEM_FLOATS (Hsz * Bn + 16 * Hsz + 16 * Bn)
#define SMEM_BYTES  (SMEM_FLOATS * 4)

__global__ __launch_bounds__(256, 1) void lstm_rec(
    const float* __restrict__ h_n, const float* __restrict__ c_n,
    const float* __restrict__ W_hh, float* __restrict__ out)
{
    extern __shared__ float sm[];
    float* h_s = sm;                       // [512][64]  (k-major, b inner)
    float* W_s = sm + Hsz * Bn;            // [16][512]  rows r=g*4+jj
    float* g_s = W_s + 16 * Hsz;           // [16][64]

    const int tid = threadIdx.x;
    const int j0  = blockIdx.x * 4;

    // W_hh rows for this block's 4 j's x 4 gates -> smem, once.
    for (int idx = tid; idx < 16 * Hsz; idx += 256) {
        int r  = idx >> 9;                 // 0..15
        int k  = idx & 511;
        int g  = r >> 2, jj = r & 3;
        W_s[idx] = W_hh[(size_t)(g * Hsz + j0 + jj) * Hsz + k];
    }

    // elementwise identity: thread owns (b, j)
    const int eb  = tid >> 2;
    const int ejj = tid & 3;
    const int ej  = j0 + ejj;
    float c_reg = c_n[eb * Hsz + ej];
    g_h[0][ej * Bn + eb] = h_n[eb * Hsz + ej];

    // dot identity: thread owns (row, 4 consecutive b)
    const int row = tid >> 4;              // 0..15
    const int bq4 = tid & 15;              // float4 index over b

    unsigned target = NBLK;
    grid_bar(target);                      // h[0] fully initialized

    for (int t = 0; t < Ssz; t++) {
        // prefetch this thread's 4 xg values (DRAM) early
        const float* xgp = g_xg + ((size_t)t * Bn + eb) * Gsz + ej;
        float xi = __ldcg(xgp + 0 * Hsz);
        float xf = __ldcg(xgp + 1 * Hsz);
        float xg = __ldcg(xgp + 2 * Hsz);
        float xo = __ldcg(xgp + 3 * Hsz);

        // copy h (ping buffer) into smem, L1-bypassed
        {
            const float4* hb  = (const float4*)g_h[t & 1];
            float4*       hs4 = (float4*)h_s;
#pragma unroll
            for (int i = 0; i < 32; i++)
                hs4[i * 256 + tid] = __ldcg(hb + i * 256 + tid);
        }
        __syncthreads();

        // dot: acc[4b] for one gate-row, K=512
        float4 acc = {0.f, 0.f, 0.f, 0.f};
        const float4* w4 = (const float4*)(W_s + row * Hsz);
        const float4* h4 = (const float4*)h_s + bq4;
#pragma unroll 4
        for (int k4 = 0; k4 < 128; k4++) {
            float4 w  = w4[k4];
            float4 h0 = h4[(k4 * 4 + 0) * 16];
            float4 h1 = h4[(k4 * 4 + 1) * 16];
            float4 h2 = h4[(k4 * 4 + 2) * 16];
            float4 h3 = h4[(k4 * 4 + 3) * 16];
            acc.x = fmaf(w.x, h0.x, acc.x); acc.x = fmaf(w.y, h1.x, acc.x);
            acc.x = fmaf(w.z, h2.x, acc.x); acc.x = fmaf(w.w, h3.x, acc.x);
            acc.y = fmaf(w.x, h0.y, acc.y); acc.y = fmaf(w.y, h1.y, acc.y);
            acc.y = fmaf(w.z, h2.y, acc.y); acc.y = fmaf(w.w, h3.y, acc.y);
            acc.z = fmaf(w.x, h0.z, acc.z); acc.z = fmaf(w.y, h1.z, acc.z);
            acc.z = fmaf(w.z, h2.z, acc.z); acc.z = fmaf(w.w, h3.z, acc.z);
            acc.w = fmaf(w.x, h0.w, acc.w); acc.w = fmaf(w.y, h1.w, acc.w);
            acc.w = fmaf(w.z, h2.w, acc.w); acc.w = fmaf(w.w, h3.w, acc.w);
        }
        *(float4*)(g_s + row * Bn + bq4 * 4) = acc;
        __syncthreads();

        // elementwise LSTM cell (torch gate order i,f,g,o)
        float gi = xi + g_s[(0 * 4 + ejj) * Bn + eb];
        float gf = xf + g_s[(1 * 4 + ejj) * Bn + eb];
        float gg = xg + g_s[(2 * 4 + ejj) * Bn + eb];
        float go = xo + g_s[(3 * 4 + ejj) * Bn + eb];
        float si = 1.f / (1.f + __expf(-gi));
        float sf = 1.f / (1.f + __expf(-gf));
        float so = 1.f / (1.f + __expf(-go));
        float tg = tanhf(gg);
        c_reg = sf * c_reg + si * tg;
        float hnew = so * tanhf(c_reg);

        out[((size_t)eb * Ssz + t) * Hsz + ej] = hnew;
        g_h[(t + 1) & 1][ej * Bn + eb] = hnew;

        target += NBLK;
        grid_bar(target);
    }
}

// ---------------------------------------------------------------------------
// kernel_launch
// inputs: 0:x 1:emb 2:h_n 3:c_n 4:W_ih 5:W_hh 6:b_ih 7:b_hh
// ---------------------------------------------------------------------------
extern "C" void kernel_launch(void* const* d_in, const int* in_sizes, int n_in,
                              void* d_out, int out_size)
{
    const float* x    = (const float*)d_in[0];
    const float* emb  = (const float*)d_in[1];
    const float* h_n  = (const float*)d_in[2];
    const float* c_n  = (const float*)d_in[3];
    const float* W_ih = (const float*)d_in[4];
    const float* W_hh = (const float*)d_in[5];
    const float* b_ih = (const float*)d_in[6];
    const float* b_hh = (const float*)d_in[7];
    float* out = (float*)d_out;

    cudaFuncSetAttribute(lstm_rec, cudaFuncAttributeMaxDynamicSharedMemorySize,
                         SMEM_BYTES);

    reset_kernel<<<1, 1>>>();
    xg_gemm<<<dim3(Gsz / BN, (Bn * Ssz) / BM), 256>>>(x, emb, W_ih, b_ih, b_hh);
    lstm_rec<<<NBLK, 256, SMEM_BYTES>>>(h_n, c_n, W_hh, out);
}

// round 4
// speedup vs baseline: 1.3743x; 1.3743x over previous
#include <cuda_runtime.h>
#include <cuda_bf16.h>
#include <mma.h>
#include <cstdint>

using namespace nvcuda;

#define Bn  64
#define Ssz 512
#define Dsz 512
#define Hsz 512
#define Gsz 2048   // 4*H

#define NBLK 128   // persistent blocks, 1 per SM

// ---------------------------------------------------------------------------
// global scratch
// ---------------------------------------------------------------------------
__device__ float         g_xg[(size_t)Ssz * Bn * Gsz];       // 256 MB
__device__ float         g_h[2][Hsz * Bn];
__device__ unsigned      g_count;
__device__ unsigned      g_done;
__device__ __nv_bfloat16 g_Ahi[(size_t)Bn * Ssz * Dsz];      // inputs hi
__device__ __nv_bfloat16 g_Alo[(size_t)Bn * Ssz * Dsz];      // inputs lo
__device__ __nv_bfloat16 g_Whi[(size_t)Gsz * Dsz];           // W_ih hi
__device__ __nv_bfloat16 g_Wlo[(size_t)Gsz * Dsz];           // W_ih lo

// ---------------------------------------------------------------------------
// Kernel 1: fp32 -> (hi,lo) bf16 split for inputs (with emb shift) and W_ih
// ---------------------------------------------------------------------------
__global__ __launch_bounds__(256) void convert_kernel(
    const float* __restrict__ x, const float* __restrict__ emb,
    const float* __restrict__ W_ih)
{
    const int A4 = (Bn * Ssz * Dsz) / 4;     // inputs float4 count
    const int T4 = A4 + (Gsz * Dsz) / 4;     // + W_ih
    for (int idx = blockIdx.x * 256 + threadIdx.x; idx < T4; idx += gridDim.x * 256) {
        const float* src;
        __nv_bfloat16 *hi, *lo;
        int off4;
        if (idx < A4) {
            int m = idx >> 7, c = idx & 127;          // 128 float4 per row
            int s = m & 511;
            src = (s == 0) ? (emb + (size_t)(m >> 9) * Dsz)
                           : (x + (size_t)(m - 1) * Dsz);
            src += c * 4;
            hi = g_Ahi; lo = g_Alo; off4 = idx;
        } else {
            int i2 = idx - A4;
            src = W_ih + (size_t)i2 * 4;
            hi = g_Whi; lo = g_Wlo; off4 = i2;
        }
        float4 v = *(const float4*)src;
        __nv_bfloat162 h01, h23, l01, l23;
        h01.x = __float2bfloat16_rn(v.x); h01.y = __float2bfloat16_rn(v.y);
        h23.x = __float2bfloat16_rn(v.z); h23.y = __float2bfloat16_rn(v.w);
        l01.x = __float2bfloat16_rn(v.x - __bfloat162float(h01.x));
        l01.y = __float2bfloat16_rn(v.y - __bfloat162float(h01.y));
        l23.x = __float2bfloat16_rn(v.z - __bfloat162float(h23.x));
        l23.y = __float2bfloat16_rn(v.w - __bfloat162float(h23.y));
        uint2 hu, lu;
        hu.x = *(uint32_t*)&h01; hu.y = *(uint32_t*)&h23;
        lu.x = *(uint32_t*)&l01; lu.y = *(uint32_t*)&l23;
        ((uint2*)hi)[off4] = hu;
        ((uint2*)lo)[off4] = lu;
    }
}

// ---------------------------------------------------------------------------
// Kernel 2: WMMA bf16 split GEMM  xg = inputs @ W_ih^T + (b_ih + b_hh)
// M=32768, N=2048, K=512. Block 128x128, KC=64, 8 warps (warp tile 32x64).
// 3 split terms hi*hi + hi*lo + lo*hi, fp32 accumulate.
// ---------------------------------------------------------------------------
#define GBM 128
#define GBN 128
#define GKC 64
#define LDA 72                              // padded bf16 leading dim
#define LDC 132                             // padded fp32 epilogue ld
#define SM_GEMM_BYTES (4 * 128 * LDA * 2)   // 73728 B (> 128*132*4)

__global__ __launch_bounds__(256) void xg_gemm_mma(
    const float* __restrict__ b_ih, const float* __restrict__ b_hh)
{
    extern __shared__ char smem[];
    __nv_bfloat16* A_hi = (__nv_bfloat16*)smem;          // [128][LDA]
    __nv_bfloat16* A_lo = A_hi + 128 * LDA;
    __nv_bfloat16* B_hi = A_lo + 128 * LDA;
    __nv_bfloat16* B_lo = B_hi + 128 * LDA;

    const int tid = threadIdx.x;
    const int wid = tid >> 5;
    const int m0 = blockIdx.y * GBM;
    const int n0 = blockIdx.x * GBN;
    const int wm = wid >> 1;                 // 0..3 -> m offset wm*32
    const int wn = wid & 1;                  // 0..1 -> n offset wn*64

    wmma::fragment<wmma::accumulator, 16, 16, 16, float> C[2][4];
#pragma unroll
    for (int i = 0; i < 2; i++)
#pragma unroll
        for (int j = 0; j < 4; j++) wmma::fill_fragment(C[i][j], 0.0f);

    for (int kc = 0; kc < Dsz / GKC; kc++) {
        const int k0 = kc * GKC;
        // stage 4 tiles of 128 rows x 64 bf16 (8 uint4 per row)
#pragma unroll
        for (int u = 0; u < 4; u++) {
            int unit = u * 256 + tid;        // 0..1023
            int row = unit >> 3, c8 = unit & 7;
            size_t ga = (size_t)(m0 + row) * Dsz + k0 + c8 * 8;
            size_t gb = (size_t)(n0 + row) * Dsz + k0 + c8 * 8;
            int so = row * LDA + c8 * 8;
            *(uint4*)(A_hi + so) = *(const uint4*)(g_Ahi + ga);
            *(uint4*)(A_lo + so) = *(const uint4*)(g_Alo + ga);
            *(uint4*)(B_hi + so) = *(const uint4*)(g_Whi + gb);
            *(uint4*)(B_lo + so) = *(const uint4*)(g_Wlo + gb);
        }
        __syncthreads();

#pragma unroll
        for (int kk = 0; kk < GKC / 16; kk++) {
            wmma::fragment<wmma::matrix_a, 16, 16, 16, __nv_bfloat16, wmma::row_major> ah[2], al[2];
            wmma::fragment<wmma::matrix_b, 16, 16, 16, __nv_bfloat16, wmma::col_major> bh[4], bl[4];
#pragma unroll
            for (int i = 0; i < 2; i++) {
                int ro = (wm * 32 + i * 16) * LDA + kk * 16;
                wmma::load_matrix_sync(ah[i], A_hi + ro, LDA);
                wmma::load_matrix_sync(al[i], A_lo + ro, LDA);
            }
#pragma unroll
            for (int j = 0; j < 4; j++) {
                int ro = (wn * 64 + j * 16) * LDA + kk * 16;
                wmma::load_matrix_sync(bh[j], B_hi + ro, LDA);
                wmma::load_matrix_sync(bl[j], B_lo + ro, LDA);
            }
#pragma unroll
            for (int i = 0; i < 2; i++)
#pragma unroll
                for (int j = 0; j < 4; j++) {
                    wmma::mma_sync(C[i][j], ah[i], bh[j], C[i][j]);
                    wmma::mma_sync(C[i][j], ah[i], bl[j], C[i][j]);
                    wmma::mma_sync(C[i][j], al[i], bh[j], C[i][j]);
                }
        }
        __syncthreads();
    }

    // epilogue: frags -> smem fp32 [128][LDC], then bias + store to g_xg
    float* Cs = (float*)smem;
#pragma unroll
    for (int i = 0; i < 2; i++)
#pragma unroll
        for (int j = 0; j < 4; j++)
            wmma::store_matrix_sync(Cs + (wm * 32 + i * 16) * LDC + wn * 64 + j * 16,
                                    C[i][j], LDC, wmma::mem_row_major);
    __syncthreads();

    {
        const int r    = tid >> 1;           // 0..127
        const int half = tid & 1;            // 64 floats each
        const int m = m0 + r;
        const int s = m & 511, b = m >> 9;
        float* orow = g_xg + ((size_t)s * Bn + b) * Gsz;
        const float* crow = Cs + r * LDC + half * 64;
#pragma unroll
        for (int q = 0; q < 16; q++) {
            int n = n0 + half * 64 + q * 4;
            float4 v  = *(const float4*)(crow + q * 4);
            float4 b1 = *(const float4*)(b_ih + n);
            float4 b2 = *(const float4*)(b_hh + n);
            v.x += b1.x + b2.x; v.y += b1.y + b2.y;
            v.z += b1.z + b2.z; v.w += b1.w + b2.w;
            *(float4*)(orow + n) = v;
        }
    }
}

// ---------------------------------------------------------------------------
// grid-wide software barrier (all NBLK blocks co-resident: 1 block/SM)
// ---------------------------------------------------------------------------
__device__ __forceinline__ void grid_bar(unsigned target)
{
    __threadfence();
    __syncthreads();
    if (threadIdx.x == 0) {
        atomicAdd(&g_count, 1u);
        volatile unsigned* p = &g_count;
        while (*p < target) { }
        __threadfence();
    }
    __syncthreads();
}

// ---------------------------------------------------------------------------
// Kernel 3: persistent recurrent LSTM.
// 128 blocks x 256 threads. Block owns 4 hidden cols (16 gate rows of W_hh,
// k-major in smem). Warp holds all 16 rows (lane&15) so W/h smem loads are
// broadcast; FMA pipe binding (~8192 cyc/step).
// ---------------------------------------------------------------------------
#define GS_STRIDE 68
#define SMEM_FLOATS (Hsz * Bn + 16 * Hsz + 16 * GS_STRIDE)
#define SMEM_BYTES  (SMEM_FLOATS * 4)

__global__ __launch_bounds__(256, 1) void lstm_rec(
    const float* __restrict__ h_n, const float* __restrict__ c_n,
    const float* __restrict__ W_hh, float* __restrict__ out)
{
    extern __shared__ float sm[];
    float* h_s = sm;                       // [512][64]  (k-major, b inner)
    float* W_s = sm + Hsz * Bn;            // [512][16]  k-major, r = g*4+jj
    float* g_s = W_s + 16 * Hsz;           // [16][GS_STRIDE]

    const int tid = threadIdx.x;
    const int j0  = blockIdx.x * 4;

    // W_hh rows (16 per block), transposed to k-major, loaded once.
    for (int idx = tid; idx < 16 * Hsz; idx += 256) {
        int k = idx >> 4;
        int r = idx & 15;
        W_s[idx] = W_hh[((size_t)(r >> 2) * Hsz + j0 + (r & 3)) * Hsz + k];
    }

    // elementwise identity: thread owns (b, j)
    const int eb  = tid >> 2;
    const int ejj = tid & 3;
    const int ej  = j0 + ejj;
    float c_reg = c_n[eb * Hsz + ej];
    g_h[0][ej * Bn + eb] = h_n[eb * Hsz + ej];

    // dot identity: warp = 16 rows x 2 b-quads (broadcast-friendly)
    const int wrp  = tid >> 5;
    const int lane = tid & 31;
    const int drow = lane & 15;            // 0..15 gate row
    const int db4  = wrp * 2 + (lane >> 4);// 0..15 -> b quad

    unsigned target = NBLK;
    grid_bar(target);                      // h[0] fully initialized

    for (int t = 0; t < Ssz; t++) {
        // prefetch xg (DRAM) early
        const float* xgp = g_xg + ((size_t)t * Bn + eb) * Gsz + ej;
        float xi = __ldcg(xgp + 0 * Hsz);
        float xf = __ldcg(xgp + 1 * Hsz);
        float xg = __ldcg(xgp + 2 * Hsz);
        float xo = __ldcg(xgp + 3 * Hsz);

        // copy h (ping buffer) into smem, L1-bypassed
        {
            const float4* hb  = (const float4*)g_h[t & 1];
            float4*       hs4 = (float4*)h_s;
#pragma unroll
            for (int i = 0; i < 32; i++)
                hs4[i * 256 + tid] = __ldcg(hb + i * 256 + tid);
        }
        __syncthreads();

        // dot: one gate row x 4 b, K=512
        float4 acc = {0.f, 0.f, 0.f, 0.f};
#pragma unroll 4
        for (int k4 = 0; k4 < 128; k4++) {
            int k = k4 * 4;
            float w0 = W_s[(k + 0) * 16 + drow];
            float w1 = W_s[(k + 1) * 16 + drow];
            float w2 = W_s[(k + 2) * 16 + drow];
            float w3 = W_s[(k + 3) * 16 + drow];
            float4 h0 = *(const float4*)(h_s + (k + 0) * Bn + db4 * 4);
            float4 h1 = *(const float4*)(h_s + (k + 1) * Bn + db4 * 4);
            float4 h2 = *(const float4*)(h_s + (k + 2) * Bn + db4 * 4);
            float4 h3 = *(const float4*)(h_s + (k + 3) * Bn + db4 * 4);
            acc.x = fmaf(w0, h0.x, acc.x); acc.x = fmaf(w1, h1.x, acc.x);
            acc.x = fmaf(w2, h2.x, acc.x); acc.x = fmaf(w3, h3.x, acc.x);
            acc.y = fmaf(w0, h0.y, acc.y); acc.y = fmaf(w1, h1.y, acc.y);
            acc.y = fmaf(w2, h2.y, acc.y); acc.y = fmaf(w3, h3.y, acc.y);
            acc.z = fmaf(w0, h0.z, acc.z); acc.z = fmaf(w1, h1.z, acc.z);
            acc.z = fmaf(w2, h2.z, acc.z); acc.z = fmaf(w3, h3.z, acc.z);
            acc.w = fmaf(w0, h0.w, acc.w); acc.w = fmaf(w1, h1.w, acc.w);
            acc.w = fmaf(w2, h2.w, acc.w); acc.w = fmaf(w3, h3.w, acc.w);
        }
        *(float4*)(g_s + drow * GS_STRIDE + db4 * 4) = acc;
        __syncthreads();

        // elementwise LSTM cell (gate order i,f,g,o)
        float gi = xi + g_s[(0 * 4 + ejj) * GS_STRIDE + eb];
        float gf = xf + g_s[(1 * 4 + ejj) * GS_STRIDE + eb];
        float gg = xg + g_s[(2 * 4 + ejj) * GS_STRIDE + eb];
        float go = xo + g_s[(3 * 4 + ejj) * GS_STRIDE + eb];
        float si = 1.f / (1.f + __expf(-gi));
        float sf = 1.f / (1.f + __expf(-gf));
        float so = 1.f / (1.f + __expf(-go));
        float tg = tanhf(gg);
        c_reg = sf * c_reg + si * tg;
        float hnew = so * tanhf(c_reg);

        out[((size_t)eb * Ssz + t) * Hsz + ej] = hnew;
        g_h[(t + 1) & 1][ej * Bn + eb] = hnew;

        target += NBLK;
        grid_bar(target);
    }

    // self-reset barrier counters for next graph replay (last block to finish)
    if (tid == 0) {
        if (atomicAdd(&g_done, 1u) == NBLK - 1) {
            g_count = 0u;
            g_done  = 0u;
            __threadfence();
        }
    }
}

// ---------------------------------------------------------------------------
// kernel_launch
// inputs: 0:x 1:emb 2:h_n 3:c_n 4:W_ih 5:W_hh 6:b_ih 7:b_hh
// ---------------------------------------------------------------------------
extern "C" void kernel_launch(void* const* d_in, const int* in_sizes, int n_in,
                              void* d_out, int out_size)
{
    const float* x    = (const float*)d_in[0];
    const float* emb  = (const float*)d_in[1];
    const float* h_n  = (const float*)d_in[2];
    const float* c_n  = (const float*)d_in[3];
    const float* W_hh = (const float*)d_in[5];
    const float* b_ih = (const float*)d_in[6];
    const float* b_hh = (const float*)d_in[7];
    const float* W_ih = (const float*)d_in[4];
    float* out = (float*)d_out;

    cudaFuncSetAttribute(xg_gemm_mma, cudaFuncAttributeMaxDynamicSharedMemorySize,
                         SM_GEMM_BYTES);
    cudaFuncSetAttribute(lstm_rec, cudaFuncAttributeMaxDynamicSharedMemorySize,
                         SMEM_BYTES);

    convert_kernel<<<1024, 256>>>(x, emb, W_ih);
    xg_gemm_mma<<<dim3(Gsz / GBN, (Bn * Ssz) / GBM), 256, SM_GEMM_BYTES>>>(b_ih, b_hh);
    lstm_rec<<<NBLK, 256, SMEM_BYTES>>>(h_n, c_n, W_hh, out);
}

// round 5
// speedup vs baseline: 2.0230x; 1.4721x over previous
#include <cuda_runtime.h>
#include <cuda_bf16.h>
#include <mma.h>
#include <cstdint>

using namespace nvcuda;

#define Bn  64
#define Ssz 512
#define Dsz 512
#define Hsz 512
#define Gsz 2048   // 4*H

#define NBLK 128   // persistent blocks, 1 per SM

// ---------------------------------------------------------------------------
// global scratch
// ---------------------------------------------------------------------------
__device__ float         g_xg[(size_t)Ssz * Bn * Gsz];       // 256 MB
__device__ __nv_bfloat16 g_hbf[2][2][Hsz * Bn];              // [ping][hi/lo][j*64+b]
__device__ unsigned      g_count;
__device__ unsigned      g_done;
__device__ __nv_bfloat16 g_Ahi[(size_t)Bn * Ssz * Dsz];      // inputs hi
__device__ __nv_bfloat16 g_Alo[(size_t)Bn * Ssz * Dsz];      // inputs lo
__device__ __nv_bfloat16 g_Whi[(size_t)Gsz * Dsz];           // W_ih hi
__device__ __nv_bfloat16 g_Wlo[(size_t)Gsz * Dsz];           // W_ih lo

// ---------------------------------------------------------------------------
// Kernel 1: fp32 -> (hi,lo) bf16 split for inputs (with emb shift) and W_ih
// ---------------------------------------------------------------------------
__global__ __launch_bounds__(256) void convert_kernel(
    const float* __restrict__ x, const float* __restrict__ emb,
    const float* __restrict__ W_ih)
{
    const int A4 = (Bn * Ssz * Dsz) / 4;
    const int T4 = A4 + (Gsz * Dsz) / 4;
    for (int idx = blockIdx.x * 256 + threadIdx.x; idx < T4; idx += gridDim.x * 256) {
        const float* src;
        __nv_bfloat16 *hi, *lo;
        int off4;
        if (idx < A4) {
            int m = idx >> 7, c = idx & 127;
            int s = m & 511;
            src = (s == 0) ? (emb + (size_t)(m >> 9) * Dsz)
                           : (x + (size_t)(m - 1) * Dsz);
            src += c * 4;
            hi = g_Ahi; lo = g_Alo; off4 = idx;
        } else {
            int i2 = idx - A4;
            src = W_ih + (size_t)i2 * 4;
            hi = g_Whi; lo = g_Wlo; off4 = i2;
        }
        float4 v = *(const float4*)src;
        __nv_bfloat162 h01, h23, l01, l23;
        h01.x = __float2bfloat16_rn(v.x); h01.y = __float2bfloat16_rn(v.y);
        h23.x = __float2bfloat16_rn(v.z); h23.y = __float2bfloat16_rn(v.w);
        l01.x = __float2bfloat16_rn(v.x - __bfloat162float(h01.x));
        l01.y = __float2bfloat16_rn(v.y - __bfloat162float(h01.y));
        l23.x = __float2bfloat16_rn(v.z - __bfloat162float(h23.x));
        l23.y = __float2bfloat16_rn(v.w - __bfloat162float(h23.y));
        uint2 hu, lu;
        hu.x = *(uint32_t*)&h01; hu.y = *(uint32_t*)&h23;
        lu.x = *(uint32_t*)&l01; lu.y = *(uint32_t*)&l23;
        ((uint2*)hi)[off4] = hu;
        ((uint2*)lo)[off4] = lu;
    }
}

// ---------------------------------------------------------------------------
// Kernel 2: WMMA bf16 split GEMM  xg = inputs @ W_ih^T + (b_ih + b_hh)
// (unchanged from round 4 — works, ~0.5 ms)
// ---------------------------------------------------------------------------
#define GBM 128
#define GBN 128
#define GKC 64
#define LDA 72
#define LDC 132
#define SM_GEMM_BYTES (4 * 128 * LDA * 2)

__global__ __launch_bounds__(256) void xg_gemm_mma(
    const float* __restrict__ b_ih, const float* __restrict__ b_hh)
{
    extern __shared__ char smem[];
    __nv_bfloat16* A_hi = (__nv_bfloat16*)smem;
    __nv_bfloat16* A_lo = A_hi + 128 * LDA;
    __nv_bfloat16* B_hi = A_lo + 128 * LDA;
    __nv_bfloat16* B_lo = B_hi + 128 * LDA;

    const int tid = threadIdx.x;
    const int wid = tid >> 5;
    const int m0 = blockIdx.y * GBM;
    const int n0 = blockIdx.x * GBN;
    const int wm = wid >> 1;
    const int wn = wid & 1;

    wmma::fragment<wmma::accumulator, 16, 16, 16, float> C[2][4];
#pragma unroll
    for (int i = 0; i < 2; i++)
#pragma unroll
        for (int j = 0; j < 4; j++) wmma::fill_fragment(C[i][j], 0.0f);

    for (int kc = 0; kc < Dsz / GKC; kc++) {
        const int k0 = kc * GKC;
#pragma unroll
        for (int u = 0; u < 4; u++) {
            int unit = u * 256 + tid;
            int row = unit >> 3, c8 = unit & 7;
            size_t ga = (size_t)(m0 + row) * Dsz + k0 + c8 * 8;
            size_t gb = (size_t)(n0 + row) * Dsz + k0 + c8 * 8;
            int so = row * LDA + c8 * 8;
            *(uint4*)(A_hi + so) = *(const uint4*)(g_Ahi + ga);
            *(uint4*)(A_lo + so) = *(const uint4*)(g_Alo + ga);
            *(uint4*)(B_hi + so) = *(const uint4*)(g_Whi + gb);
            *(uint4*)(B_lo + so) = *(const uint4*)(g_Wlo + gb);
        }
        __syncthreads();

#pragma unroll
        for (int kk = 0; kk < GKC / 16; kk++) {
            wmma::fragment<wmma::matrix_a, 16, 16, 16, __nv_bfloat16, wmma::row_major> ah[2], al[2];
            wmma::fragment<wmma::matrix_b, 16, 16, 16, __nv_bfloat16, wmma::col_major> bh[4], bl[4];
#pragma unroll
            for (int i = 0; i < 2; i++) {
                int ro = (wm * 32 + i * 16) * LDA + kk * 16;
                wmma::load_matrix_sync(ah[i], A_hi + ro, LDA);
                wmma::load_matrix_sync(al[i], A_lo + ro, LDA);
            }
#pragma unroll
            for (int j = 0; j < 4; j++) {
                int ro = (wn * 64 + j * 16) * LDA + kk * 16;
                wmma::load_matrix_sync(bh[j], B_hi + ro, LDA);
                wmma::load_matrix_sync(bl[j], B_lo + ro, LDA);
            }
#pragma unroll
            for (int i = 0; i < 2; i++)
#pragma unroll
                for (int j = 0; j < 4; j++) {
                    wmma::mma_sync(C[i][j], ah[i], bh[j], C[i][j]);
                    wmma::mma_sync(C[i][j], ah[i], bl[j], C[i][j]);
                    wmma::mma_sync(C[i][j], al[i], bh[j], C[i][j]);
                }
        }
        __syncthreads();
    }

    float* Cs = (float*)smem;
#pragma unroll
    for (int i = 0; i < 2; i++)
#pragma unroll
        for (int j = 0; j < 4; j++)
            wmma::store_matrix_sync(Cs + (wm * 32 + i * 16) * LDC + wn * 64 + j * 16,
                                    C[i][j], LDC, wmma::mem_row_major);
    __syncthreads();

    {
        const int r    = tid >> 1;
        const int half = tid & 1;
        const int m = m0 + r;
        const int s = m & 511, b = m >> 9;
        float* orow = g_xg + ((size_t)s * Bn + b) * Gsz;
        const float* crow = Cs + r * LDC + half * 64;
#pragma unroll
        for (int q = 0; q < 16; q++) {
            int n = n0 + half * 64 + q * 4;
            float4 v  = *(const float4*)(crow + q * 4);
            float4 b1 = *(const float4*)(b_ih + n);
            float4 b2 = *(const float4*)(b_hh + n);
            v.x += b1.x + b2.x; v.y += b1.y + b2.y;
            v.z += b1.z + b2.z; v.w += b1.w + b2.w;
            *(float4*)(orow + n) = v;
        }
    }
}

// ---------------------------------------------------------------------------
// grid-wide software barrier (all NBLK blocks co-resident: 1 block/SM)
// ---------------------------------------------------------------------------
__device__ __forceinline__ void grid_bar(unsigned target)
{
    __threadfence();
    __syncthreads();
    if (threadIdx.x == 0) {
        atomicAdd(&g_count, 1u);
        volatile unsigned* p = &g_count;
        while (*p < target) { }
        __threadfence();
    }
    __syncthreads();
}

// ---------------------------------------------------------------------------
// Kernel 3: persistent recurrent LSTM on tensor cores.
// 128 blocks x 256 threads (8 warps). Block owns 4 hidden cols = 16 gate rows.
// W_hh rows split once to bf16 hi/lo in smem. Each step:
//   stage h (bf16 hi/lo, 128KB) from global ping -> smem,
//   each warp: one 16(row)x16(b) tile over K=256 half via wmma (3 split terms),
//   reduce 2 K-halves in smem, elementwise cell, write h as bf16 hi/lo pair.
// ---------------------------------------------------------------------------
#define LDW 520                 // W smem leading dim (bf16), conflict-free LDSM
#define LDH 72                  // h smem leading dim (bf16)
#define LDCS 68                 // C partial leading dim (fp32)
#define OFF_WHI 0
#define OFF_WLO (16 * LDW)
#define OFF_HHI (2 * 16 * LDW)
#define OFF_HLO (2 * 16 * LDW + Hsz * LDH)
#define OFF_CS  (2 * 16 * LDW + 2 * Hsz * LDH)          // in bf16 units, 4B-aligned
#define REC_SMEM_BYTES ((OFF_CS) * 2 + 2 * 16 * LDCS * 4)

__global__ __launch_bounds__(256, 1) void lstm_rec_tc(
    const float* __restrict__ h_n, const float* __restrict__ c_n,
    const float* __restrict__ W_hh, float* __restrict__ out)
{
    extern __shared__ char smem[];
    __nv_bfloat16* Whi_s = (__nv_bfloat16*)smem + OFF_WHI;   // [16][LDW]
    __nv_bfloat16* Wlo_s = (__nv_bfloat16*)smem + OFF_WLO;
    __nv_bfloat16* Hhi_s = (__nv_bfloat16*)smem + OFF_HHI;   // [512][LDH]
    __nv_bfloat16* Hlo_s = (__nv_bfloat16*)smem + OFF_HLO;
    float*         Cs    = (float*)((__nv_bfloat16*)smem + OFF_CS); // [2][16][LDCS]

    const int tid = threadIdx.x;
    const int wid = tid >> 5;
    const int j0  = blockIdx.x * 4;

    // stage W_hh rows (r = gate*4 + jj), split to bf16 hi/lo — once.
    for (int idx = tid; idx < 16 * Hsz; idx += 256) {
        int r = idx >> 9, k = idx & 511;
        float w = W_hh[((size_t)(r >> 2) * Hsz + j0 + (r & 3)) * Hsz + k];
        __nv_bfloat16 hi = __float2bfloat16_rn(w);
        __nv_bfloat16 lo = __float2bfloat16_rn(w - __bfloat162float(hi));
        Whi_s[r * LDW + k] = hi;
        Wlo_s[r * LDW + k] = lo;
    }

    // elementwise identity: thread owns (b, j)
    const int eb  = tid >> 2;
    const int ejj = tid & 3;
    const int ej  = j0 + ejj;
    float c_reg = c_n[eb * Hsz + ej];
    {
        float h0 = h_n[eb * Hsz + ej];
        __nv_bfloat16 hi = __float2bfloat16_rn(h0);
        g_hbf[0][0][ej * Bn + eb] = hi;
        g_hbf[0][1][ej * Bn + eb] = __float2bfloat16_rn(h0 - __bfloat162float(hi));
    }

    // mma identity: warp -> (k-half, b-tile)
    const int kh = wid >> 2;               // 0..1 -> K half
    const int nb = wid & 3;                // 0..3 -> 16-b tile

    unsigned target = NBLK;
    grid_bar(target);                      // h[0] + W staging visible

    for (int t = 0; t < Ssz; t++) {
        // prefetch xg (DRAM) early
        const float* xgp = g_xg + ((size_t)t * Bn + eb) * Gsz + ej;
        float xi = __ldcg(xgp + 0 * Hsz);
        float xf = __ldcg(xgp + 1 * Hsz);
        float xg = __ldcg(xgp + 2 * Hsz);
        float xo = __ldcg(xgp + 3 * Hsz);

        // stage h hi/lo (64KB each) -> smem, L1-bypassed
        {
            const uint4* shi = (const uint4*)g_hbf[t & 1][0];  // 4096 uint4
            const uint4* slo = (const uint4*)g_hbf[t & 1][1];
            uint4* dhi = (uint4*)Hhi_s;                        // ld 72 bf16 = 9 uint4
            uint4* dlo = (uint4*)Hlo_s;
#pragma unroll
            for (int it = 0; it < 16; it++) {
                int i = it * 256 + tid;
                int k = i >> 3, c = i & 7;
                dhi[k * 9 + c] = __ldcg(shi + i);
                dlo[k * 9 + c] = __ldcg(slo + i);
            }
        }
        __syncthreads();

        // warp mma: C(16 rows x 16 b) over K=256 half, 3 split terms
        {
            wmma::fragment<wmma::accumulator, 16, 16, 16, float> cf;
            wmma::fill_fragment(cf, 0.0f);
#pragma unroll
            for (int kk = 0; kk < 16; kk++) {
                int k = kh * 256 + kk * 16;
                wmma::fragment<wmma::matrix_a, 16, 16, 16, __nv_bfloat16, wmma::row_major> ah, al;
                wmma::fragment<wmma::matrix_b, 16, 16, 16, __nv_bfloat16, wmma::row_major> bh, bl;
                wmma::load_matrix_sync(ah, Whi_s + k, LDW);
                wmma::load_matrix_sync(al, Wlo_s + k, LDW);
                wmma::load_matrix_sync(bh, Hhi_s + k * LDH + nb * 16, LDH);
                wmma::load_matrix_sync(bl, Hlo_s + k * LDH + nb * 16, LDH);
                wmma::mma_sync(cf, ah, bh, cf);
                wmma::mma_sync(cf, ah, bl, cf);
                wmma::mma_sync(cf, al, bh, cf);
            }
            wmma::store_matrix_sync(Cs + kh * 16 * LDCS + nb * 16, cf, LDCS,
                                    wmma::mem_row_major);
        }
        __syncthreads();

        // elementwise LSTM cell (gate order i,f,g,o); rows r = gate*4 + jj
        const float* C0 = Cs;
        const float* C1 = Cs + 16 * LDCS;
        float gi = xi + C0[(0  + ejj) * LDCS + eb] + C1[(0  + ejj) * LDCS + eb];
        float gf = xf + C0[(4  + ejj) * LDCS + eb] + C1[(4  + ejj) * LDCS + eb];
        float gg = xg + C0[(8  + ejj) * LDCS + eb] + C1[(8  + ejj) * LDCS + eb];
        float go = xo + C0[(12 + ejj) * LDCS + eb] + C1[(12 + ejj) * LDCS + eb];
        float si = 1.f / (1.f + __expf(-gi));
        float sf = 1.f / (1.f + __expf(-gf));
        float so = 1.f / (1.f + __expf(-go));
        float tg = tanhf(gg);
        c_reg = sf * c_reg + si * tg;
        float hnew = so * tanhf(c_reg);

        out[((size_t)eb * Ssz + t) * Hsz + ej] = hnew;
        {
            __nv_bfloat16 hi = __float2bfloat16_rn(hnew);
            g_hbf[(t + 1) & 1][0][ej * Bn + eb] = hi;
            g_hbf[(t + 1) & 1][1][ej * Bn + eb] =
                __float2bfloat16_rn(hnew - __bfloat162float(hi));
        }

        target += NBLK;
        grid_bar(target);
    }

    // self-reset barrier counters for next graph replay
    if (tid == 0) {
        if (atomicAdd(&g_done, 1u) == NBLK - 1) {
            g_count = 0u;
            g_done  = 0u;
            __threadfence();
        }
    }
}

// ---------------------------------------------------------------------------
// kernel_launch
// inputs: 0:x 1:emb 2:h_n 3:c_n 4:W_ih 5:W_hh 6:b_ih 7:b_hh
// ---------------------------------------------------------------------------
extern "C" void kernel_launch(void* const* d_in, const int* in_sizes, int n_in,
                              void* d_out, int out_size)
{
    const float* x    = (const float*)d_in[0];
    const float* emb  = (const float*)d_in[1];
    const float* h_n  = (const float*)d_in[2];
    const float* c_n  = (const float*)d_in[3];
    const float* W_ih = (const float*)d_in[4];
    const float* W_hh = (const float*)d_in[5];
    const float* b_ih = (const float*)d_in[6];
    const float* b_hh = (const float*)d_in[7];
    float* out = (float*)d_out;

    cudaFuncSetAttribute(xg_gemm_mma, cudaFuncAttributeMaxDynamicSharedMemorySize,
                         SM_GEMM_BYTES);
    cudaFuncSetAttribute(lstm_rec_tc, cudaFuncAttributeMaxDynamicSharedMemorySize,
                         REC_SMEM_BYTES);

    convert_kernel<<<1024, 256>>>(x, emb, W_ih);
    xg_gemm_mma<<<dim3(Gsz / GBN, (Bn * Ssz) / GBM), 256, SM_GEMM_BYTES>>>(b_ih, b_hh);
    lstm_rec_tc<<<NBLK, 256, REC_SMEM_BYTES>>>(h_n, c_n, W_hh, out);
}

// round 6
// speedup vs baseline: 2.3640x; 1.1686x over previous
#include <cuda_runtime.h>
#include <cuda_bf16.h>
#include <mma.h>
#include <cstdint>

using namespace nvcuda;

#define Bn  64
#define Ssz 512
#define Dsz 512
#define Hsz 512
#define Gsz 2048   // 4*H

// recurrent tiling: 4 b-columns x 32 j-slices = 128 blocks
#define NBS 4      // b-slices
#define NJ  32     // j-slice blocks per b-column
#define JT  16     // j per block
#define BT  16     // b per block

// ---------------------------------------------------------------------------
// global scratch
// ---------------------------------------------------------------------------
__device__ float         g_xg[(size_t)Ssz * Bn * Gsz];       // 256 MB
__device__ __nv_bfloat16 g_hsl[2][NBS][2][Hsz * BT];         // [ping][bs][hi/lo][j*16+bb]
__device__ unsigned      g_cnt[NBS * 32];                    // 128B-spaced counters
__device__ unsigned      g_done;
__device__ __nv_bfloat16 g_Ahi[(size_t)Bn * Ssz * Dsz];      // inputs hi
__device__ __nv_bfloat16 g_Alo[(size_t)Bn * Ssz * Dsz];      // inputs lo
__device__ __nv_bfloat16 g_Whi[(size_t)Gsz * Dsz];           // W_ih hi
__device__ __nv_bfloat16 g_Wlo[(size_t)Gsz * Dsz];           // W_ih lo

// ---------------------------------------------------------------------------
// Kernel 1: fp32 -> (hi,lo) bf16 split for inputs (with emb shift) and W_ih
// ---------------------------------------------------------------------------
__global__ __launch_bounds__(256) void convert_kernel(
    const float* __restrict__ x, const float* __restrict__ emb,
    const float* __restrict__ W_ih)
{
    const int A4 = (Bn * Ssz * Dsz) / 4;
    const int T4 = A4 + (Gsz * Dsz) / 4;
    for (int idx = blockIdx.x * 256 + threadIdx.x; idx < T4; idx += gridDim.x * 256) {
        const float* src;
        __nv_bfloat16 *hi, *lo;
        int off4;
        if (idx < A4) {
            int m = idx >> 7, c = idx & 127;
            int s = m & 511;
            src = (s == 0) ? (emb + (size_t)(m >> 9) * Dsz)
                           : (x + (size_t)(m - 1) * Dsz);
            src += c * 4;
            hi = g_Ahi; lo = g_Alo; off4 = idx;
        } else {
            int i2 = idx - A4;
            src = W_ih + (size_t)i2 * 4;
            hi = g_Whi; lo = g_Wlo; off4 = i2;
        }
        float4 v = *(const float4*)src;
        __nv_bfloat162 h01, h23, l01, l23;
        h01.x = __float2bfloat16_rn(v.x); h01.y = __float2bfloat16_rn(v.y);
        h23.x = __float2bfloat16_rn(v.z); h23.y = __float2bfloat16_rn(v.w);
        l01.x = __float2bfloat16_rn(v.x - __bfloat162float(h01.x));
        l01.y = __float2bfloat16_rn(v.y - __bfloat162float(h01.y));
        l23.x = __float2bfloat16_rn(v.z - __bfloat162float(h23.x));
        l23.y = __float2bfloat16_rn(v.w - __bfloat162float(h23.y));
        uint2 hu, lu;
        hu.x = *(uint32_t*)&h01; hu.y = *(uint32_t*)&h23;
        lu.x = *(uint32_t*)&l01; lu.y = *(uint32_t*)&l23;
        ((uint2*)hi)[off4] = hu;
        ((uint2*)lo)[off4] = lu;
    }
}

// ---------------------------------------------------------------------------
// Kernel 2: WMMA bf16 split GEMM  xg = inputs @ W_ih^T + (b_ih + b_hh)
// (unchanged — works, ~0.5 ms)
// ---------------------------------------------------------------------------
#define GBM 128
#define GBN 128
#define GKC 64
#define LDA 72
#define LDC 132
#define SM_GEMM_BYTES (4 * 128 * LDA * 2)

__global__ __launch_bounds__(256) void xg_gemm_mma(
    const float* __restrict__ b_ih, const float* __restrict__ b_hh)
{
    extern __shared__ char smem[];
    __nv_bfloat16* A_hi = (__nv_bfloat16*)smem;
    __nv_bfloat16* A_lo = A_hi + 128 * LDA;
    __nv_bfloat16* B_hi = A_lo + 128 * LDA;
    __nv_bfloat16* B_lo = B_hi + 128 * LDA;

    const int tid = threadIdx.x;
    const int wid = tid >> 5;
    const int m0 = blockIdx.y * GBM;
    const int n0 = blockIdx.x * GBN;
    const int wm = wid >> 1;
    const int wn = wid & 1;

    wmma::fragment<wmma::accumulator, 16, 16, 16, float> C[2][4];
#pragma unroll
    for (int i = 0; i < 2; i++)
#pragma unroll
        for (int j = 0; j < 4; j++) wmma::fill_fragment(C[i][j], 0.0f);

    for (int kc = 0; kc < Dsz / GKC; kc++) {
        const int k0 = kc * GKC;
#pragma unroll
        for (int u = 0; u < 4; u++) {
            int unit = u * 256 + tid;
            int row = unit >> 3, c8 = unit & 7;
            size_t ga = (size_t)(m0 + row) * Dsz + k0 + c8 * 8;
            size_t gb = (size_t)(n0 + row) * Dsz + k0 + c8 * 8;
            int so = row * LDA + c8 * 8;
            *(uint4*)(A_hi + so) = *(const uint4*)(g_Ahi + ga);
            *(uint4*)(A_lo + so) = *(const uint4*)(g_Alo + ga);
            *(uint4*)(B_hi + so) = *(const uint4*)(g_Whi + gb);
            *(uint4*)(B_lo + so) = *(const uint4*)(g_Wlo + gb);
        }
        __syncthreads();

#pragma unroll
        for (int kk = 0; kk < GKC / 16; kk++) {
            wmma::fragment<wmma::matrix_a, 16, 16, 16, __nv_bfloat16, wmma::row_major> ah[2], al[2];
            wmma::fragment<wmma::matrix_b, 16, 16, 16, __nv_bfloat16, wmma::col_major> bh[4], bl[4];
#pragma unroll
            for (int i = 0; i < 2; i++) {
                int ro = (wm * 32 + i * 16) * LDA + kk * 16;
                wmma::load_matrix_sync(ah[i], A_hi + ro, LDA);
                wmma::load_matrix_sync(al[i], A_lo + ro, LDA);
            }
#pragma unroll
            for (int j = 0; j < 4; j++) {
                int ro = (wn * 64 + j * 16) * LDA + kk * 16;
                wmma::load_matrix_sync(bh[j], B_hi + ro, LDA);
                wmma::load_matrix_sync(bl[j], B_lo + ro, LDA);
            }
#pragma unroll
            for (int i = 0; i < 2; i++)
#pragma unroll
                for (int j = 0; j < 4; j++) {
                    wmma::mma_sync(C[i][j], ah[i], bh[j], C[i][j]);
                    wmma::mma_sync(C[i][j], ah[i], bl[j], C[i][j]);
                    wmma::mma_sync(C[i][j], al[i], bh[j], C[i][j]);
                }
        }
        __syncthreads();
    }

    float* Cs = (float*)smem;
#pragma unroll
    for (int i = 0; i < 2; i++)
#pragma unroll
        for (int j = 0; j < 4; j++)
            wmma::store_matrix_sync(Cs + (wm * 32 + i * 16) * LDC + wn * 64 + j * 16,
                                    C[i][j], LDC, wmma::mem_row_major);
    __syncthreads();

    {
        const int r    = tid >> 1;
        const int half = tid & 1;
        const int m = m0 + r;
        const int s = m & 511, b = m >> 9;
        float* orow = g_xg + ((size_t)s * Bn + b) * Gsz;
        const float* crow = Cs + r * LDC + half * 64;
#pragma unroll
        for (int q = 0; q < 16; q++) {
            int n = n0 + half * 64 + q * 4;
            float4 v  = *(const float4*)(crow + q * 4);
            float4 b1 = *(const float4*)(b_ih + n);
            float4 b2 = *(const float4*)(b_hh + n);
            v.x += b1.x + b2.x; v.y += b1.y + b2.y;
            v.z += b1.z + b2.z; v.w += b1.w + b2.w;
            *(float4*)(orow + n) = v;
        }
    }
}

// ---------------------------------------------------------------------------
// per-b-column barrier (32 blocks each, monotonic counter)
// ---------------------------------------------------------------------------
__device__ __forceinline__ void col_bar(unsigned* cnt, unsigned target)
{
    __threadfence();
    __syncthreads();
    if (threadIdx.x == 0) {
        atomicAdd(cnt, 1u);
        volatile unsigned* p = cnt;
        while (*p < target) { }
        __threadfence();
    }
    __syncthreads();
}

// ---------------------------------------------------------------------------
// Kernel 3: persistent recurrent LSTM, 2-D tiled (b-slices independent).
// 128 blocks = 4 b-columns x 32 j-slices. Block owns 16 j x 16 b:
//   W_hh 64 gate-rows split to bf16 hi/lo in smem (130KB, loaded once).
//   Per step: stage h slab (512 j x 16 b, hi/lo, 32KB) from its b-column,
//   8 warps: 4 row-tiles x 2 K-halves of wmma (3 split terms),
//   cell in registers, publish h slab slice, barrier over 32 blocks only.
// ---------------------------------------------------------------------------
#define LDW  520                // W smem ld (bf16): conflict-free LDSM
#define LDH  24                 // h smem ld (bf16): conflict-free LDSM
#define LDCS 20                 // C partial ld (fp32)
#define OFF_WHI 0
#define OFF_WLO (64 * LDW)                               // bf16 units
#define OFF_HHI (2 * 64 * LDW)
#define OFF_HLO (2 * 64 * LDW + Hsz * LDH)
#define OFF_CS  (2 * 64 * LDW + 2 * Hsz * LDH)
#define REC_SMEM_BYTES (OFF_CS * 2 + 2 * 64 * LDCS * 4)  // 192512

__global__ __launch_bounds__(256, 1) void lstm_rec_tc2(
    const float* __restrict__ h_n, const float* __restrict__ c_n,
    const float* __restrict__ W_hh, float* __restrict__ out)
{
    extern __shared__ char smem[];
    __nv_bfloat16* Whi_s = (__nv_bfloat16*)smem + OFF_WHI;   // [64][LDW]
    __nv_bfloat16* Wlo_s = (__nv_bfloat16*)smem + OFF_WLO;
    __nv_bfloat16* Hhi_s = (__nv_bfloat16*)smem + OFF_HHI;   // [512][LDH]
    __nv_bfloat16* Hlo_s = (__nv_bfloat16*)smem + OFF_HLO;
    float*         Cs    = (float*)((__nv_bfloat16*)smem + OFF_CS); // [2][64][LDCS]

    const int tid = threadIdx.x;
    const int wid = tid >> 5;
    const int bs  = blockIdx.x & 3;        // b-column
    const int js  = blockIdx.x >> 2;       // j-slice
    unsigned* cnt = &g_cnt[bs * 32];

    // stage W_hh slice: 64 rows (r = gate*16 + jj), split hi/lo — once.
    for (int idx = tid; idx < 64 * Hsz; idx += 256) {
        int r = idx >> 9, k = idx & 511;
        float w = W_hh[((size_t)(r >> 4) * Hsz + js * JT + (r & 15)) * Hsz + k];
        __nv_bfloat16 hi = __float2bfloat16_rn(w);
        __nv_bfloat16 lo = __float2bfloat16_rn(w - __bfloat162float(hi));
        Whi_s[r * LDW + k] = hi;
        Wlo_s[r * LDW + k] = lo;
    }

    // cell identity: tid = bb*16 + jj  (xg loads coalesced over jj)
    const int jj = tid & 15;
    const int bb = tid >> 4;
    const int j  = js * JT + jj;
    const int b  = bs * BT + bb;
    float c_reg = c_n[b * Hsz + j];
    {
        float h0 = h_n[b * Hsz + j];
        __nv_bfloat16 hi = __float2bfloat16_rn(h0);
        g_hsl[0][bs][0][j * BT + bb] = hi;
        g_hsl[0][bs][1][j * BT + bb] =
            __float2bfloat16_rn(h0 - __bfloat162float(hi));
    }

    // mma identity: warp -> (K-half, row-tile)
    const int kh = wid >> 2;               // 0..1
    const int rt = wid & 3;                // 0..3 -> rows rt*16..rt*16+15

    unsigned target = NJ;
    col_bar(cnt, target);                  // h[0] published

    for (int t = 0; t < Ssz; t++) {
        // prefetch xg (coalesced: 16 consecutive j per (b,gate))
        const float* xgp = g_xg + ((size_t)t * Bn + b) * Gsz + j;
        float xi = __ldcg(xgp + 0 * Hsz);
        float xf = __ldcg(xgp + 1 * Hsz);
        float xg = __ldcg(xgp + 2 * Hsz);
        float xo = __ldcg(xgp + 3 * Hsz);

        // stage h slab (this b-column only): 1024 uint4 per buffer
        {
            const uint4* shi = (const uint4*)g_hsl[t & 1][bs][0];
            const uint4* slo = (const uint4*)g_hsl[t & 1][bs][1];
#pragma unroll
            for (int it = 0; it < 4; it++) {
                int i = it * 256 + tid;       // 0..1023
                int j2 = i >> 1, half = i & 1;
                *(uint4*)(Hhi_s + j2 * LDH + half * 8) = __ldcg(shi + i);
                *(uint4*)(Hlo_s + j2 * LDH + half * 8) = __ldcg(slo + i);
            }
        }
        __syncthreads();

        // warp mma: C(16 rows x 16 b) over K=256 half, 3 split terms
        {
            wmma::fragment<wmma::accumulator, 16, 16, 16, float> cf;
            wmma::fill_fragment(cf, 0.0f);
#pragma unroll
            for (int kk = 0; kk < 16; kk++) {
                int k = kh * 256 + kk * 16;
                wmma::fragment<wmma::matrix_a, 16, 16, 16, __nv_bfloat16, wmma::row_major> ah, al;
                wmma::fragment<wmma::matrix_b, 16, 16, 16, __nv_bfloat16, wmma::row_major> bh, bl;
                wmma::load_matrix_sync(ah, Whi_s + rt * 16 * LDW + k, LDW);
                wmma::load_matrix_sync(al, Wlo_s + rt * 16 * LDW + k, LDW);
                wmma::load_matrix_sync(bh, Hhi_s + k * LDH, LDH);
                wmma::load_matrix_sync(bl, Hlo_s + k * LDH, LDH);
                wmma::mma_sync(cf, ah, bh, cf);
                wmma::mma_sync(cf, ah, bl, cf);
                wmma::mma_sync(cf, al, bh, cf);
            }
            wmma::store_matrix_sync(Cs + (kh * 64 + rt * 16) * LDCS, cf, LDCS,
                                    wmma::mem_row_major);
        }
        __syncthreads();

        // elementwise LSTM cell; C rows r = gate*16 + jj, reduce 2 K-halves
        const float* C0 = Cs;
        const float* C1 = Cs + 64 * LDCS;
        float gi = xi + C0[(0  + jj) * LDCS + bb] + C1[(0  + jj) * LDCS + bb];
        float gf = xf + C0[(16 + jj) * LDCS + bb] + C1[(16 + jj) * LDCS + bb];
        float gg = xg + C0[(32 + jj) * LDCS + bb] + C1[(32 + jj) * LDCS + bb];
        float go = xo + C0[(48 + jj) * LDCS + bb] + C1[(48 + jj) * LDCS + bb];
        float si = 1.f / (1.f + __expf(-gi));
        float sf = 1.f / (1.f + __expf(-gf));
        float so = 1.f / (1.f + __expf(-go));
        float tg = tanhf(gg);
        c_reg = sf * c_reg + si * tg;
        float hnew = so * tanhf(c_reg);

        out[((size_t)b * Ssz + t) * Hsz + j] = hnew;
        {
            __nv_bfloat16 hi = __float2bfloat16_rn(hnew);
            g_hsl[(t + 1) & 1][bs][0][j * BT + bb] = hi;
            g_hsl[(t + 1) & 1][bs][1][j * BT + bb] =
                __float2bfloat16_rn(hnew - __bfloat162float(hi));
        }

        target += NJ;
        col_bar(cnt, target);
    }

    // self-reset counters for next graph replay (last block chip-wide)
    if (tid == 0) {
        if (atomicAdd(&g_done, 1u) == NBS * NJ - 1) {
            for (int i = 0; i < NBS; i++) g_cnt[i * 32] = 0u;
            g_done = 0u;
            __threadfence();
        }
    }
}

// ---------------------------------------------------------------------------
// kernel_launch
// inputs: 0:x 1:emb 2:h_n 3:c_n 4:W_ih 5:W_hh 6:b_ih 7:b_hh
// ---------------------------------------------------------------------------
extern "C" void kernel_launch(void* const* d_in, const int* in_sizes, int n_in,
                              void* d_out, int out_size)
{
    const float* x    = (const float*)d_in[0];
    const float* emb  = (const float*)d_in[1];
    const float* h_n  = (const float*)d_in[2];
    const float* c_n  = (const float*)d_in[3];
    const float* W_ih = (const float*)d_in[4];
    const float* W_hh = (const float*)d_in[5];
    const float* b_ih = (const float*)d_in[6];
    const float* b_hh = (const float*)d_in[7];
    float* out = (float*)d_out;

    cudaFuncSetAttribute(xg_gemm_mma, cudaFuncAttributeMaxDynamicSharedMemorySize,
                         SM_GEMM_BYTES);
    cudaFuncSetAttribute(lstm_rec_tc2, cudaFuncAttributeMaxDynamicSharedMemorySize,
                         REC_SMEM_BYTES);

    convert_kernel<<<1024, 256>>>(x, emb, W_ih);
    xg_gemm_mma<<<dim3(Gsz / GBN, (Bn * Ssz) / GBM), 256, SM_GEMM_BYTES>>>(b_ih, b_hh);
    lstm_rec_tc2<<<NBS * NJ, 256, REC_SMEM_BYTES>>>(h_n, c_n, W_hh, out);
}

// round 7
// speedup vs baseline: 2.4510x; 1.0368x over previous
#include <cuda_runtime.h>
#include <cuda_bf16.h>
#include <mma.h>
#include <cstdint>

using namespace nvcuda;

#define Bn  64
#define Ssz 512
#define Dsz 512
#define Hsz 512
#define Gsz 2048   // 4*H

// recurrent tiling: 4 b-columns x 32 j-slices = 128 blocks, 512 threads each
#define NBS 4      // b-slices
#define NJ  32     // j-slice blocks per b-column
#define JT  16     // j per block
#define BT  16     // b per block

// ---------------------------------------------------------------------------
// global scratch
// ---------------------------------------------------------------------------
__device__ float         g_xg[(size_t)Ssz * Bn * Gsz];       // 256 MB
__device__ __nv_bfloat16 g_hsl[2][NBS][2][Hsz * BT];         // [ping][bs][hi/lo][j*16+bb]
__device__ unsigned      g_cnt[NBS * 32];                    // 128B-spaced counters
__device__ unsigned      g_done;
__device__ __nv_bfloat16 g_Ahi[(size_t)Bn * Ssz * Dsz];      // inputs hi
__device__ __nv_bfloat16 g_Alo[(size_t)Bn * Ssz * Dsz];      // inputs lo
__device__ __nv_bfloat16 g_Whi[(size_t)Gsz * Dsz];           // W_ih hi
__device__ __nv_bfloat16 g_Wlo[(size_t)Gsz * Dsz];           // W_ih lo

// ---------------------------------------------------------------------------
// light device-scope sync primitives (no membar.gl -> no L1 flush)
// ---------------------------------------------------------------------------
__device__ __forceinline__ void red_release(unsigned* p) {
    asm volatile("red.release.gpu.global.add.u32 [%0], 1;" :: "l"(p) : "memory");
}
__device__ __forceinline__ unsigned ld_acquire(unsigned* p) {
    unsigned v;
    asm volatile("ld.acquire.gpu.global.u32 %0, [%1];" : "=r"(v) : "l"(p) : "memory");
    return v;
}

// ---------------------------------------------------------------------------
// Kernel 1: fp32 -> (hi,lo) bf16 split for inputs (with emb shift) and W_ih
// ---------------------------------------------------------------------------
__global__ __launch_bounds__(256) void convert_kernel(
    const float* __restrict__ x, const float* __restrict__ emb,
    const float* __restrict__ W_ih)
{
    const int A4 = (Bn * Ssz * Dsz) / 4;
    const int T4 = A4 + (Gsz * Dsz) / 4;
    for (int idx = blockIdx.x * 256 + threadIdx.x; idx < T4; idx += gridDim.x * 256) {
        const float* src;
        __nv_bfloat16 *hi, *lo;
        int off4;
        if (idx < A4) {
            int m = idx >> 7, c = idx & 127;
            int s = m & 511;
            src = (s == 0) ? (emb + (size_t)(m >> 9) * Dsz)
                           : (x + (size_t)(m - 1) * Dsz);
            src += c * 4;
            hi = g_Ahi; lo = g_Alo; off4 = idx;
        } else {
            int i2 = idx - A4;
            src = W_ih + (size_t)i2 * 4;
            hi = g_Whi; lo = g_Wlo; off4 = i2;
        }
        float4 v = *(const float4*)src;
        __nv_bfloat162 h01, h23, l01, l23;
        h01.x = __float2bfloat16_rn(v.x); h01.y = __float2bfloat16_rn(v.y);
        h23.x = __float2bfloat16_rn(v.z); h23.y = __float2bfloat16_rn(v.w);
        l01.x = __float2bfloat16_rn(v.x - __bfloat162float(h01.x));
        l01.y = __float2bfloat16_rn(v.y - __bfloat162float(h01.y));
        l23.x = __float2bfloat16_rn(v.z - __bfloat162float(h23.x));
        l23.y = __float2bfloat16_rn(v.w - __bfloat162float(h23.y));
        uint2 hu, lu;
        hu.x = *(uint32_t*)&h01; hu.y = *(uint32_t*)&h23;
        lu.x = *(uint32_t*)&l01; lu.y = *(uint32_t*)&l23;
        ((uint2*)hi)[off4] = hu;
        ((uint2*)lo)[off4] = lu;
    }
}

// ---------------------------------------------------------------------------
// Kernel 2: WMMA bf16 split GEMM  xg = inputs @ W_ih^T + (b_ih + b_hh)
// (unchanged — works)
// ---------------------------------------------------------------------------
#define GBM 128
#define GBN 128
#define GKC 64
#define LDA 72
#define LDC 132
#define SM_GEMM_BYTES (4 * 128 * LDA * 2)

__global__ __launch_bounds__(256) void xg_gemm_mma(
    const float* __restrict__ b_ih, const float* __restrict__ b_hh)
{
    extern __shared__ char smem[];
    __nv_bfloat16* A_hi = (__nv_bfloat16*)smem;
    __nv_bfloat16* A_lo = A_hi + 128 * LDA;
    __nv_bfloat16* B_hi = A_lo + 128 * LDA;
    __nv_bfloat16* B_lo = B_hi + 128 * LDA;

    const int tid = threadIdx.x;
    const int wid = tid >> 5;
    const int m0 = blockIdx.y * GBM;
    const int n0 = blockIdx.x * GBN;
    const int wm = wid >> 1;
    const int wn = wid & 1;

    wmma::fragment<wmma::accumulator, 16, 16, 16, float> C[2][4];
#pragma unroll
    for (int i = 0; i < 2; i++)
#pragma unroll
        for (int j = 0; j < 4; j++) wmma::fill_fragment(C[i][j], 0.0f);

    for (int kc = 0; kc < Dsz / GKC; kc++) {
        const int k0 = kc * GKC;
#pragma unroll
        for (int u = 0; u < 4; u++) {
            int unit = u * 256 + tid;
            int row = unit >> 3, c8 = unit & 7;
            size_t ga = (size_t)(m0 + row) * Dsz + k0 + c8 * 8;
            size_t gb = (size_t)(n0 + row) * Dsz + k0 + c8 * 8;
            int so = row * LDA + c8 * 8;
            *(uint4*)(A_hi + so) = *(const uint4*)(g_Ahi + ga);
            *(uint4*)(A_lo + so) = *(const uint4*)(g_Alo + ga);
            *(uint4*)(B_hi + so) = *(const uint4*)(g_Whi + gb);
            *(uint4*)(B_lo + so) = *(const uint4*)(g_Wlo + gb);
        }
        __syncthreads();

#pragma unroll
        for (int kk = 0; kk < GKC / 16; kk++) {
            wmma::fragment<wmma::matrix_a, 16, 16, 16, __nv_bfloat16, wmma::row_major> ah[2], al[2];
            wmma::fragment<wmma::matrix_b, 16, 16, 16, __nv_bfloat16, wmma::col_major> bh[4], bl[4];
#pragma unroll
            for (int i = 0; i < 2; i++) {
                int ro = (wm * 32 + i * 16) * LDA + kk * 16;
                wmma::load_matrix_sync(ah[i], A_hi + ro, LDA);
                wmma::load_matrix_sync(al[i], A_lo + ro, LDA);
            }
#pragma unroll
            for (int j = 0; j < 4; j++) {
                int ro = (wn * 64 + j * 16) * LDA + kk * 16;
                wmma::load_matrix_sync(bh[j], B_hi + ro, LDA);
                wmma::load_matrix_sync(bl[j], B_lo + ro, LDA);
            }
#pragma unroll
            for (int i = 0; i < 2; i++)
#pragma unroll
                for (int j = 0; j < 4; j++) {
                    wmma::mma_sync(C[i][j], ah[i], bh[j], C[i][j]);
                    wmma::mma_sync(C[i][j], ah[i], bl[j], C[i][j]);
                    wmma::mma_sync(C[i][j], al[i], bh[j], C[i][j]);
                }
        }
        __syncthreads();
    }

    float* Cs = (float*)smem;
#pragma unroll
    for (int i = 0; i < 2; i++)
#pragma unroll
        for (int j = 0; j < 4; j++)
            wmma::store_matrix_sync(Cs + (wm * 32 + i * 16) * LDC + wn * 64 + j * 16,
                                    C[i][j], LDC, wmma::mem_row_major);
    __syncthreads();

    {
        const int r    = tid >> 1;
        const int half = tid & 1;
        const int m = m0 + r;
        const int s = m & 511, b = m >> 9;
        float* orow = g_xg + ((size_t)s * Bn + b) * Gsz;
        const float* crow = Cs + r * LDC + half * 64;
#pragma unroll
        for (int q = 0; q < 16; q++) {
            int n = n0 + half * 64 + q * 4;
            float4 v  = *(const float4*)(crow + q * 4);
            float4 b1 = *(const float4*)(b_ih + n);
            float4 b2 = *(const float4*)(b_hh + n);
            v.x += b1.x + b2.x; v.y += b1.y + b2.y;
            v.z += b1.z + b2.z; v.w += b1.w + b2.w;
            *(float4*)(orow + n) = v;
        }
    }
}

// ---------------------------------------------------------------------------
// Kernel 3: persistent recurrent LSTM, 512 threads (16 warps = 4/SMSP).
// 128 blocks = 4 b-columns x 32 j-slices. Block owns 16 j x 16 b.
// mma: 16 warps = 4 K-quarters x 4 row-tiles; 3 independent accumulators.
// Barrier: per-thread release-red + acquire poll (no membar.gl / L1 flush).
// ---------------------------------------------------------------------------
#define LDW  520                // W smem ld (bf16)
#define LDH  24                 // h smem ld (bf16)
#define LDCS 20                 // C partial ld (fp32)
#define OFF_WHI 0
#define OFF_WLO (64 * LDW)                               // bf16 units
#define OFF_HHI (2 * 64 * LDW)
#define OFF_HLO (2 * 64 * LDW + Hsz * LDH)
#define OFF_CS  (2 * 64 * LDW + 2 * Hsz * LDH)
#define REC_SMEM_BYTES (OFF_CS * 2 + 4 * 64 * LDCS * 4)  // 202752

__global__ __launch_bounds__(512, 1) void lstm_rec_tc3(
    const float* __restrict__ h_n, const float* __restrict__ c_n,
    const float* __restrict__ W_hh, float* __restrict__ out)
{
    extern __shared__ char smem[];
    __nv_bfloat16* Whi_s = (__nv_bfloat16*)smem + OFF_WHI;   // [64][LDW]
    __nv_bfloat16* Wlo_s = (__nv_bfloat16*)smem + OFF_WLO;
    __nv_bfloat16* Hhi_s = (__nv_bfloat16*)smem + OFF_HHI;   // [512][LDH]
    __nv_bfloat16* Hlo_s = (__nv_bfloat16*)smem + OFF_HLO;
    float*         Cs    = (float*)((__nv_bfloat16*)smem + OFF_CS); // [4][64][LDCS]

    const int tid = threadIdx.x;
    const int wid = tid >> 5;
    const int bs  = blockIdx.x & 3;        // b-column
    const int js  = blockIdx.x >> 2;       // j-slice
    unsigned* cnt = &g_cnt[bs * 32];

    // stage W_hh slice: 64 rows (r = gate*16 + jj), split hi/lo — once.
    for (int idx = tid; idx < 64 * Hsz; idx += 512) {
        int r = idx >> 9, k = idx & 511;
        float w = W_hh[((size_t)(r >> 4) * Hsz + js * JT + (r & 15)) * Hsz + k];
        __nv_bfloat16 hi = __float2bfloat16_rn(w);
        __nv_bfloat16 lo = __float2bfloat16_rn(w - __bfloat162float(hi));
        Whi_s[r * LDW + k] = hi;
        Wlo_s[r * LDW + k] = lo;
    }

    // cell identity (threads 0..255): tid = bb*16 + jj
    const int jj = tid & 15;
    const int bb = (tid >> 4) & 15;
    const bool is_cell = (tid < 256);
    const int j  = js * JT + jj;
    const int b  = bs * BT + bb;
    float c_reg = 0.f;
    if (is_cell) {
        c_reg = c_n[b * Hsz + j];
        float h0 = h_n[b * Hsz + j];
        __nv_bfloat16 hi = __float2bfloat16_rn(h0);
        __nv_bfloat16 lo = __float2bfloat16_rn(h0 - __bfloat162float(hi));
        __stcg((unsigned short*)&g_hsl[0][bs][0][j * BT + bb], __bfloat16_as_ushort(hi));
        __stcg((unsigned short*)&g_hsl[0][bs][1][j * BT + bb], __bfloat16_as_ushort(lo));
        red_release(cnt);
    }

    // mma identity: warp -> (K-quarter, row-tile)
    const int kh = wid >> 2;               // 0..3 -> K quarter (128)
    const int rt = wid & 3;                // 0..3 -> rows rt*16..+15

    unsigned target = NJ * 256;            // h[0] published
    if (tid == 0) while (ld_acquire(cnt) < target) { }
    __syncthreads();                       // also covers W staging

    for (int t = 0; t < Ssz; t++) {
        // prefetch xg (coalesced over jj), consumed in cell phase
        float xi, xf, xg, xo;
        if (is_cell) {
            const float* xgp = g_xg + ((size_t)t * Bn + b) * Gsz + j;
            xi = __ldcg(xgp + 0 * Hsz);
            xf = __ldcg(xgp + 1 * Hsz);
            xg = __ldcg(xgp + 2 * Hsz);
            xo = __ldcg(xgp + 3 * Hsz);
        }

        // stage h slab (this b-column): 2048 uint4, 4 per thread
        {
            const uint4* shi = (const uint4*)g_hsl[t & 1][bs][0];
            const uint4* slo = (const uint4*)g_hsl[t & 1][bs][1];
#pragma unroll
            for (int it = 0; it < 2; it++) {
                int i = it * 512 + tid;       // 0..1023
                int j2 = i >> 1, half = i & 1;
                *(uint4*)(Hhi_s + j2 * LDH + half * 8) = __ldcg(shi + i);
                *(uint4*)(Hlo_s + j2 * LDH + half * 8) = __ldcg(slo + i);
            }
        }
        __syncthreads();

        // warp mma: C(16 rows x 16 b) over K=128 quarter, 3 independent accs
        {
            wmma::fragment<wmma::accumulator, 16, 16, 16, float> chh, chl, clh;
            wmma::fill_fragment(chh, 0.0f);
            wmma::fill_fragment(chl, 0.0f);
            wmma::fill_fragment(clh, 0.0f);
#pragma unroll
            for (int kk = 0; kk < 8; kk++) {
                int k = kh * 128 + kk * 16;
                wmma::fragment<wmma::matrix_a, 16, 16, 16, __nv_bfloat16, wmma::row_major> ah, al;
                wmma::fragment<wmma::matrix_b, 16, 16, 16, __nv_bfloat16, wmma::row_major> bh, bl;
                wmma::load_matrix_sync(ah, Whi_s + rt * 16 * LDW + k, LDW);
                wmma::load_matrix_sync(al, Wlo_s + rt * 16 * LDW + k, LDW);
                wmma::load_matrix_sync(bh, Hhi_s + k * LDH, LDH);
                wmma::load_matrix_sync(bl, Hlo_s + k * LDH, LDH);
                wmma::mma_sync(chh, ah, bh, chh);
                wmma::mma_sync(chl, ah, bl, chl);
                wmma::mma_sync(clh, al, bh, clh);
            }
#pragma unroll
            for (int i = 0; i < chh.num_elements; i++)
                chh.x[i] += chl.x[i] + clh.x[i];
            wmma::store_matrix_sync(Cs + (kh * 64 + rt * 16) * LDCS, chh, LDCS,
                                    wmma::mem_row_major);
        }
        __syncthreads();

        // elementwise LSTM cell; reduce 4 K-quarters
        if (is_cell) {
            float gi = xi, gf = xf, gg = xg, go = xo;
#pragma unroll
            for (int q = 0; q < 4; q++) {
                const float* Cq = Cs + q * 64 * LDCS;
                gi += Cq[(0  + jj) * LDCS + bb];
                gf += Cq[(16 + jj) * LDCS + bb];
                gg += Cq[(32 + jj) * LDCS + bb];
                go += Cq[(48 + jj) * LDCS + bb];
            }
            float si = 1.f / (1.f + __expf(-gi));
            float sf = 1.f / (1.f + __expf(-gf));
            float so = 1.f / (1.f + __expf(-go));
            float tg = tanhf(gg);
            c_reg = sf * c_reg + si * tg;
            float hnew = so * tanhf(c_reg);

            __nv_bfloat16 hi = __float2bfloat16_rn(hnew);
            __nv_bfloat16 lo = __float2bfloat16_rn(hnew - __bfloat162float(hi));
            int pp = (t + 1) & 1;
            __stcg((unsigned short*)&g_hsl[pp][bs][0][j * BT + bb], __bfloat16_as_ushort(hi));
            __stcg((unsigned short*)&g_hsl[pp][bs][1][j * BT + bb], __bfloat16_as_ushort(lo));
            red_release(cnt);

            out[((size_t)b * Ssz + t) * Hsz + j] = hnew;
        }

        target += NJ * 256;
        if (tid == 0) while (ld_acquire(cnt) < target) { }
        __syncthreads();
    }

    // self-reset counters for next graph replay (last block chip-wide)
    if (tid == 0) {
        if (atomicAdd(&g_done, 1u) == NBS * NJ - 1) {
            for (int i = 0; i < NBS; i++) g_cnt[i * 32] = 0u;
            g_done = 0u;
            __threadfence();
        }
    }
}

// ---------------------------------------------------------------------------
// kernel_launch
// inputs: 0:x 1:emb 2:h_n 3:c_n 4:W_ih 5:W_hh 6:b_ih 7:b_hh
// ---------------------------------------------------------------------------
extern "C" void kernel_launch(void* const* d_in, const int* in_sizes, int n_in,
                              void* d_out, int out_size)
{
    const float* x    = (const float*)d_in[0];
    const float* emb  = (const float*)d_in[1];
    const float* h_n  = (const float*)d_in[2];
    const float* c_n  = (const float*)d_in[3];
    const float* W_ih = (const float*)d_in[4];
    const float* W_hh = (const float*)d_in[5];
    const float* b_ih = (const float*)d_in[6];
    const float* b_hh = (const float*)d_in[7];
    float* out = (float*)d_out;

    cudaFuncSetAttribute(xg_gemm_mma, cudaFuncAttributeMaxDynamicSharedMemorySize,
                         SM_GEMM_BYTES);
    cudaFuncSetAttribute(lstm_rec_tc3, cudaFuncAttributeMaxDynamicSharedMemorySize,
                         REC_SMEM_BYTES);

    convert_kernel<<<1024, 256>>>(x, emb, W_ih);
    xg_gemm_mma<<<dim3(Gsz / GBN, (Bn * Ssz) / GBM), 256, SM_GEMM_BYTES>>>(b_ih, b_hh);
    lstm_rec_tc3<<<NBS * NJ, 512, REC_SMEM_BYTES>>>(h_n, c_n, W_hh, out);
}

// round 8
// speedup vs baseline: 2.5933x; 1.0581x over previous
#include <cuda_runtime.h>
#include <cuda_bf16.h>
#include <mma.h>
#include <cstdint>

using namespace nvcuda;

#define Bn  64
#define Ssz 512
#define Dsz 512
#define Hsz 512
#define Gsz 2048   // 4*H

// recurrent tiling: 4 b-columns x 32 j-slices = 128 blocks, 512 threads each
#define NBS 4      // b-slices
#define NJ  32     // j-slice blocks per b-column
#define JT  16     // j per block
#define BT  16     // b per block

// ---------------------------------------------------------------------------
// global scratch
// ---------------------------------------------------------------------------
__device__ float         g_xg[(size_t)Ssz * Bn * Gsz];       // 256 MB
__device__ __nv_bfloat16 g_hsl[2][NBS][2][Hsz * BT];         // [ping][bs][hi/lo][j*16+bb]
__device__ unsigned      g_cnt[NBS * 32];                    // 128B-spaced counters
__device__ unsigned      g_done;
__device__ __nv_bfloat16 g_Ahi[(size_t)Bn * Ssz * Dsz];      // inputs hi
__device__ __nv_bfloat16 g_Alo[(size_t)Bn * Ssz * Dsz];      // inputs lo
__device__ __nv_bfloat16 g_Whi[(size_t)Gsz * Dsz];           // W_ih hi
__device__ __nv_bfloat16 g_Wlo[(size_t)Gsz * Dsz];           // W_ih lo

// ---------------------------------------------------------------------------
// light device-scope sync primitives (no membar.gl -> no L1 flush)
// ---------------------------------------------------------------------------
__device__ __forceinline__ void red_release(unsigned* p) {
    asm volatile("red.release.gpu.global.add.u32 [%0], 1;" :: "l"(p) : "memory");
}
__device__ __forceinline__ unsigned ld_acquire(unsigned* p) {
    unsigned v;
    asm volatile("ld.acquire.gpu.global.u32 %0, [%1];" : "=r"(v) : "l"(p) : "memory");
    return v;
}

// ---------------------------------------------------------------------------
// Kernel 1: fp32 -> (hi,lo) bf16 split for inputs (with emb shift) and W_ih
// ---------------------------------------------------------------------------
__global__ __launch_bounds__(256) void convert_kernel(
    const float* __restrict__ x, const float* __restrict__ emb,
    const float* __restrict__ W_ih)
{
    const int A4 = (Bn * Ssz * Dsz) / 4;
    const int T4 = A4 + (Gsz * Dsz) / 4;
    for (int idx = blockIdx.x * 256 + threadIdx.x; idx < T4; idx += gridDim.x * 256) {
        const float* src;
        __nv_bfloat16 *hi, *lo;
        int off4;
        if (idx < A4) {
            int m = idx >> 7, c = idx & 127;
            int s = m & 511;
            src = (s == 0) ? (emb + (size_t)(m >> 9) * Dsz)
                           : (x + (size_t)(m - 1) * Dsz);
            src += c * 4;
            hi = g_Ahi; lo = g_Alo; off4 = idx;
        } else {
            int i2 = idx - A4;
            src = W_ih + (size_t)i2 * 4;
            hi = g_Whi; lo = g_Wlo; off4 = i2;
        }
        float4 v = *(const float4*)src;
        __nv_bfloat162 h01, h23, l01, l23;
        h01.x = __float2bfloat16_rn(v.x); h01.y = __float2bfloat16_rn(v.y);
        h23.x = __float2bfloat16_rn(v.z); h23.y = __float2bfloat16_rn(v.w);
        l01.x = __float2bfloat16_rn(v.x - __bfloat162float(h01.x));
        l01.y = __float2bfloat16_rn(v.y - __bfloat162float(h01.y));
        l23.x = __float2bfloat16_rn(v.z - __bfloat162float(h23.x));
        l23.y = __float2bfloat16_rn(v.w - __bfloat162float(h23.y));
        uint2 hu, lu;
        hu.x = *(uint32_t*)&h01; hu.y = *(uint32_t*)&h23;
        lu.x = *(uint32_t*)&l01; lu.y = *(uint32_t*)&l23;
        ((uint2*)hi)[off4] = hu;
        ((uint2*)lo)[off4] = lu;
    }
}

// ---------------------------------------------------------------------------
// Kernel 2: WMMA bf16 split GEMM  xg = inputs @ W_ih^T + (b_ih + b_hh)
// (unchanged — works)
// ---------------------------------------------------------------------------
#define GBM 128
#define GBN 128
#define GKC 64
#define LDA 72
#define LDC 132
#define SM_GEMM_BYTES (4 * 128 * LDA * 2)

__global__ __launch_bounds__(256) void xg_gemm_mma(
    const float* __restrict__ b_ih, const float* __restrict__ b_hh)
{
    extern __shared__ char smem[];
    __nv_bfloat16* A_hi = (__nv_bfloat16*)smem;
    __nv_bfloat16* A_lo = A_hi + 128 * LDA;
    __nv_bfloat16* B_hi = A_lo + 128 * LDA;
    __nv_bfloat16* B_lo = B_hi + 128 * LDA;

    const int tid = threadIdx.x;
    const int wid = tid >> 5;
    const int m0 = blockIdx.y * GBM;
    const int n0 = blockIdx.x * GBN;
    const int wm = wid >> 1;
    const int wn = wid & 1;

    wmma::fragment<wmma::accumulator, 16, 16, 16, float> C[2][4];
#pragma unroll
    for (int i = 0; i < 2; i++)
#pragma unroll
        for (int j = 0; j < 4; j++) wmma::fill_fragment(C[i][j], 0.0f);

    for (int kc = 0; kc < Dsz / GKC; kc++) {
        const int k0 = kc * GKC;
#pragma unroll
        for (int u = 0; u < 4; u++) {
            int unit = u * 256 + tid;
            int row = unit >> 3, c8 = unit & 7;
            size_t ga = (size_t)(m0 + row) * Dsz + k0 + c8 * 8;
            size_t gb = (size_t)(n0 + row) * Dsz + k0 + c8 * 8;
            int so = row * LDA + c8 * 8;
            *(uint4*)(A_hi + so) = *(const uint4*)(g_Ahi + ga);
            *(uint4*)(A_lo + so) = *(const uint4*)(g_Alo + ga);
            *(uint4*)(B_hi + so) = *(const uint4*)(g_Whi + gb);
            *(uint4*)(B_lo + so) = *(const uint4*)(g_Wlo + gb);
        }
        __syncthreads();

#pragma unroll
        for (int kk = 0; kk < GKC / 16; kk++) {
            wmma::fragment<wmma::matrix_a, 16, 16, 16, __nv_bfloat16, wmma::row_major> ah[2], al[2];
            wmma::fragment<wmma::matrix_b, 16, 16, 16, __nv_bfloat16, wmma::col_major> bh[4], bl[4];
#pragma unroll
            for (int i = 0; i < 2; i++) {
                int ro = (wm * 32 + i * 16) * LDA + kk * 16;
                wmma::load_matrix_sync(ah[i], A_hi + ro, LDA);
                wmma::load_matrix_sync(al[i], A_lo + ro, LDA);
            }
#pragma unroll
            for (int j = 0; j < 4; j++) {
                int ro = (wn * 64 + j * 16) * LDA + kk * 16;
                wmma::load_matrix_sync(bh[j], B_hi + ro, LDA);
                wmma::load_matrix_sync(bl[j], B_lo + ro, LDA);
            }
#pragma unroll
            for (int i = 0; i < 2; i++)
#pragma unroll
                for (int j = 0; j < 4; j++) {
                    wmma::mma_sync(C[i][j], ah[i], bh[j], C[i][j]);
                    wmma::mma_sync(C[i][j], ah[i], bl[j], C[i][j]);
                    wmma::mma_sync(C[i][j], al[i], bh[j], C[i][j]);
                }
        }
        __syncthreads();
    }

    float* Cs = (float*)smem;
#pragma unroll
    for (int i = 0; i < 2; i++)
#pragma unroll
        for (int j = 0; j < 4; j++)
            wmma::store_matrix_sync(Cs + (wm * 32 + i * 16) * LDC + wn * 64 + j * 16,
                                    C[i][j], LDC, wmma::mem_row_major);
    __syncthreads();

    {
        const int r    = tid >> 1;
        const int half = tid & 1;
        const int m = m0 + r;
        const int s = m & 511, b = m >> 9;
        float* orow = g_xg + ((size_t)s * Bn + b) * Gsz;
        const float* crow = Cs + r * LDC + half * 64;
#pragma unroll
        for (int q = 0; q < 16; q++) {
            int n = n0 + half * 64 + q * 4;
            float4 v  = *(const float4*)(crow + q * 4);
            float4 b1 = *(const float4*)(b_ih + n);
            float4 b2 = *(const float4*)(b_hh + n);
            v.x += b1.x + b2.x; v.y += b1.y + b2.y;
            v.z += b1.z + b2.z; v.w += b1.w + b2.w;
            *(float4*)(orow + n) = v;
        }
    }
}

// ---------------------------------------------------------------------------
// Kernel 3: persistent recurrent LSTM, 512 threads (16 warps = 4/SMSP).
// 128 blocks = 4 b-columns x 32 j-slices. Block owns 16 j x 16 b.
// mma: 16 warps = 4 K-quarters x 4 row-tiles; 3 independent accumulators.
// Barrier: ONE release-arrival per block (grid.sync pattern: stcg stores,
// __syncthreads (cta happens-before), tid0 red.release + acquire poll).
// Release cumulativity covers the bar-synced stores; no membar.gl/L1 flush,
// no single-address atomic storm (32 arrivals/step/column, was 8192).
// ---------------------------------------------------------------------------
#define LDW  520                // W smem ld (bf16)
#define LDH  24                 // h smem ld (bf16)
#define LDCS 20                 // C partial ld (fp32)
#define OFF_WHI 0
#define OFF_WLO (64 * LDW)                               // bf16 units
#define OFF_HHI (2 * 64 * LDW)
#define OFF_HLO (2 * 64 * LDW + Hsz * LDH)
#define OFF_CS  (2 * 64 * LDW + 2 * Hsz * LDH)
#define REC_SMEM_BYTES (OFF_CS * 2 + 4 * 64 * LDCS * 4)  // 202752

__global__ __launch_bounds__(512, 1) void lstm_rec_tc4(
    const float* __restrict__ h_n, const float* __restrict__ c_n,
    const float* __restrict__ W_hh, float* __restrict__ out)
{
    extern __shared__ char smem[];
    __nv_bfloat16* Whi_s = (__nv_bfloat16*)smem + OFF_WHI;   // [64][LDW]
    __nv_bfloat16* Wlo_s = (__nv_bfloat16*)smem + OFF_WLO;
    __nv_bfloat16* Hhi_s = (__nv_bfloat16*)smem + OFF_HHI;   // [512][LDH]
    __nv_bfloat16* Hlo_s = (__nv_bfloat16*)smem + OFF_HLO;
    float*         Cs    = (float*)((__nv_bfloat16*)smem + OFF_CS); // [4][64][LDCS]

    const int tid = threadIdx.x;
    const int wid = tid >> 5;
    const int bs  = blockIdx.x & 3;        // b-column
    const int js  = blockIdx.x >> 2;       // j-slice
    unsigned* cnt = &g_cnt[bs * 32];

    // stage W_hh slice: 64 rows (r = gate*16 + jj), split hi/lo — once.
    for (int idx = tid; idx < 64 * Hsz; idx += 512) {
        int r = idx >> 9, k = idx & 511;
        float w = W_hh[((size_t)(r >> 4) * Hsz + js * JT + (r & 15)) * Hsz + k];
        __nv_bfloat16 hi = __float2bfloat16_rn(w);
        __nv_bfloat16 lo = __float2bfloat16_rn(w - __bfloat162float(hi));
        Whi_s[r * LDW + k] = hi;
        Wlo_s[r * LDW + k] = lo;
    }

    // cell identity (threads 0..255): tid = bb*16 + jj
    const int jj = tid & 15;
    const int bb = (tid >> 4) & 15;
    const bool is_cell = (tid < 256);
    const int j  = js * JT + jj;
    const int b  = bs * BT + bb;
    float c_reg = 0.f;
    if (is_cell) {
        c_reg = c_n[b * Hsz + j];
        float h0 = h_n[b * Hsz + j];
        __nv_bfloat16 hi = __float2bfloat16_rn(h0);
        __nv_bfloat16 lo = __float2bfloat16_rn(h0 - __bfloat162float(hi));
        __stcg((unsigned short*)&g_hsl[0][bs][0][j * BT + bb], __bfloat16_as_ushort(hi));
        __stcg((unsigned short*)&g_hsl[0][bs][1][j * BT + bb], __bfloat16_as_ushort(lo));
    }
    __syncthreads();                       // h[0] stores + W staging done (cta)

    // mma identity: warp -> (K-quarter, row-tile)
    const int kh = wid >> 2;               // 0..3 -> K quarter (128)
    const int rt = wid & 3;                // 0..3 -> rows rt*16..+15

    unsigned target = NJ;                  // one arrival per block
    if (tid == 0) {
        red_release(cnt);
        while (ld_acquire(cnt) < target) { }
    }
    __syncthreads();

    for (int t = 0; t < Ssz; t++) {
        // prefetch xg (coalesced over jj), consumed in cell phase
        float xi, xf, xg, xo;
        if (is_cell) {
            const float* xgp = g_xg + ((size_t)t * Bn + b) * Gsz + j;
            xi = __ldcg(xgp + 0 * Hsz);
            xf = __ldcg(xgp + 1 * Hsz);
            xg = __ldcg(xgp + 2 * Hsz);
            xo = __ldcg(xgp + 3 * Hsz);
        }

        // stage h slab (this b-column): 2048 uint4, 4 per thread
        {
            const uint4* shi = (const uint4*)g_hsl[t & 1][bs][0];
            const uint4* slo = (const uint4*)g_hsl[t & 1][bs][1];
#pragma unroll
            for (int it = 0; it < 2; it++) {
                int i = it * 512 + tid;       // 0..1023
                int j2 = i >> 1, half = i & 1;
                *(uint4*)(Hhi_s + j2 * LDH + half * 8) = __ldcg(shi + i);
                *(uint4*)(Hlo_s + j2 * LDH + half * 8) = __ldcg(slo + i);
            }
        }
        __syncthreads();

        // warp mma: C(16 rows x 16 b) over K=128 quarter, 3 independent accs
        {
            wmma::fragment<wmma::accumulator, 16, 16, 16, float> chh, chl, clh;
            wmma::fill_fragment(chh, 0.0f);
            wmma::fill_fragment(chl, 0.0f);
            wmma::fill_fragment(clh, 0.0f);
#pragma unroll
            for (int kk = 0; kk < 8; kk++) {
                int k = kh * 128 + kk * 16;
                wmma::fragment<wmma::matrix_a, 16, 16, 16, __nv_bfloat16, wmma::row_major> ah, al;
                wmma::fragment<wmma::matrix_b, 16, 16, 16, __nv_bfloat16, wmma::row_major> bh, bl;
                wmma::load_matrix_sync(ah, Whi_s + rt * 16 * LDW + k, LDW);
                wmma::load_matrix_sync(al, Wlo_s + rt * 16 * LDW + k, LDW);
                wmma::load_matrix_sync(bh, Hhi_s + k * LDH, LDH);
                wmma::load_matrix_sync(bl, Hlo_s + k * LDH, LDH);
                wmma::mma_sync(chh, ah, bh, chh);
                wmma::mma_sync(chl, ah, bl, chl);
                wmma::mma_sync(clh, al, bh, clh);
            }
#pragma unroll
            for (int i = 0; i < chh.num_elements; i++)
                chh.x[i] += chl.x[i] + clh.x[i];
            wmma::store_matrix_sync(Cs + (kh * 64 + rt * 16) * LDCS, chh, LDCS,
                                    wmma::mem_row_major);
        }
        __syncthreads();

        // elementwise LSTM cell; reduce 4 K-quarters
        if (is_cell) {
            float gi = xi, gf = xf, gg = xg, go = xo;
#pragma unroll
            for (int q = 0; q < 4; q++) {
                const float* Cq = Cs + q * 64 * LDCS;
                gi += Cq[(0  + jj) * LDCS + bb];
                gf += Cq[(16 + jj) * LDCS + bb];
                gg += Cq[(32 + jj) * LDCS + bb];
                go += Cq[(48 + jj) * LDCS + bb];
            }
            float si = 1.f / (1.f + __expf(-gi));
            float sf = 1.f / (1.f + __expf(-gf));
            float so = 1.f / (1.f + __expf(-go));
            float tg = tanhf(gg);
            c_reg = sf * c_reg + si * tg;
            float hnew = so * tanhf(c_reg);

            __nv_bfloat16 hi = __float2bfloat16_rn(hnew);
            __nv_bfloat16 lo = __float2bfloat16_rn(hnew - __bfloat162float(hi));
            int pp = (t + 1) & 1;
            __stcg((unsigned short*)&g_hsl[pp][bs][0][j * BT + bb], __bfloat16_as_ushort(hi));
            __stcg((unsigned short*)&g_hsl[pp][bs][1][j * BT + bb], __bfloat16_as_ushort(lo));

            out[((size_t)b * Ssz + t) * Hsz + j] = hnew;
        }
        __syncthreads();                   // publish stores happen-before arrival

        target += NJ;
        if (tid == 0) {
            red_release(cnt);              // release: covers bar-synced stcg stores
            while (ld_acquire(cnt) < target) { }
        }
        __syncthreads();
    }

    // self-reset counters for next graph replay (last block chip-wide)
    if (tid == 0) {
        if (atomicAdd(&g_done, 1u) == NBS * NJ - 1) {
            for (int i = 0; i < NBS; i++) g_cnt[i * 32] = 0u;
            g_done = 0u;
            __threadfence();
        }
    }
}

// ---------------------------------------------------------------------------
// kernel_launch
// inputs: 0:x 1:emb 2:h_n 3:c_n 4:W_ih 5:W_hh 6:b_ih 7:b_hh
// ---------------------------------------------------------------------------
extern "C" void kernel_launch(void* const* d_in, const int* in_sizes, int n_in,
                              void* d_out, int out_size)
{
    const float* x    = (const float*)d_in[0];
    const float* emb  = (const float*)d_in[1];
    const float* h_n  = (const float*)d_in[2];
    const float* c_n  = (const float*)d_in[3];
    const float* W_ih = (const float*)d_in[4];
    const float* W_hh = (const float*)d_in[5];
    const float* b_ih = (const float*)d_in[6];
    const float* b_hh = (const float*)d_in[7];
    float* out = (float*)d_out;

    cudaFuncSetAttribute(xg_gemm_mma, cudaFuncAttributeMaxDynamicSharedMemorySize,
                         SM_GEMM_BYTES);
    cudaFuncSetAttribute(lstm_rec_tc4, cudaFuncAttributeMaxDynamicSharedMemorySize,
                         REC_SMEM_BYTES);

    convert_kernel<<<1024, 256>>>(x, emb, W_ih);
    xg_gemm_mma<<<dim3(Gsz / GBN, (Bn * Ssz) / GBM), 256, SM_GEMM_BYTES>>>(b_ih, b_hh);
    lstm_rec_tc4<<<NBS * NJ, 512, REC_SMEM_BYTES>>>(h_n, c_n, W_hh, out);
}

// round 9
// speedup vs baseline: 2.8912x; 1.1149x over previous
#include <cuda_runtime.h>
#include <cuda_bf16.h>
#include <mma.h>
#include <cstdint>

using namespace nvcuda;

#define Bn  64
#define Ssz 512
#define Dsz 512
#define Hsz 512
#define Gsz 2048   // 4*H

// recurrent tiling: 4 b-columns x 32 j-slices = 128 blocks, 512 threads each
#define NBS 4      // b-slices
#define NJ  32     // j-slice blocks per b-column
#define JT  16     // j per block
#define BT  16     // b per block

// ---------------------------------------------------------------------------
// global scratch
// ---------------------------------------------------------------------------
__device__ float         g_xg[(size_t)Ssz * Bn * Gsz];       // 256 MB
__device__ __nv_bfloat16 g_hsl[2][NBS][2][Hsz * BT];         // [ping][bs][hi/lo][j*16+bb]
__device__ unsigned      g_cnt[NBS * 32];                    // 128B-spaced counters
__device__ unsigned      g_done;
__device__ __nv_bfloat16 g_Ahi[(size_t)Bn * Ssz * Dsz];      // inputs hi
__device__ __nv_bfloat16 g_Alo[(size_t)Bn * Ssz * Dsz];      // inputs lo
__device__ __nv_bfloat16 g_Whi[(size_t)Gsz * Dsz];           // W_ih hi
__device__ __nv_bfloat16 g_Wlo[(size_t)Gsz * Dsz];           // W_ih lo

// ---------------------------------------------------------------------------
// light device-scope sync primitives (no membar.gl -> no L1 flush)
// ---------------------------------------------------------------------------
__device__ __forceinline__ void red_release(unsigned* p) {
    asm volatile("red.release.gpu.global.add.u32 [%0], 1;" :: "l"(p) : "memory");
}
__device__ __forceinline__ unsigned ld_acquire(unsigned* p) {
    unsigned v;
    asm volatile("ld.acquire.gpu.global.u32 %0, [%1];" : "=r"(v) : "l"(p) : "memory");
    return v;
}

// ---------------------------------------------------------------------------
// Kernel 1: fp32 -> (hi,lo) bf16 split for inputs (with emb shift) and W_ih
// ---------------------------------------------------------------------------
__global__ __launch_bounds__(256) void convert_kernel(
    const float* __restrict__ x, const float* __restrict__ emb,
    const float* __restrict__ W_ih)
{
    const int A4 = (Bn * Ssz * Dsz) / 4;
    const int T4 = A4 + (Gsz * Dsz) / 4;
    for (int idx = blockIdx.x * 256 + threadIdx.x; idx < T4; idx += gridDim.x * 256) {
        const float* src;
        __nv_bfloat16 *hi, *lo;
        int off4;
        if (idx < A4) {
            int m = idx >> 7, c = idx & 127;
            int s = m & 511;
            src = (s == 0) ? (emb + (size_t)(m >> 9) * Dsz)
                           : (x + (size_t)(m - 1) * Dsz);
            src += c * 4;
            hi = g_Ahi; lo = g_Alo; off4 = idx;
        } else {
            int i2 = idx - A4;
            src = W_ih + (size_t)i2 * 4;
            hi = g_Whi; lo = g_Wlo; off4 = i2;
        }
        float4 v = *(const float4*)src;
        __nv_bfloat162 h01, h23, l01, l23;
        h01.x = __float2bfloat16_rn(v.x); h01.y = __float2bfloat16_rn(v.y);
        h23.x = __float2bfloat16_rn(v.z); h23.y = __float2bfloat16_rn(v.w);
        l01.x = __float2bfloat16_rn(v.x - __bfloat162float(h01.x));
        l01.y = __float2bfloat16_rn(v.y - __bfloat162float(h01.y));
        l23.x = __float2bfloat16_rn(v.z - __bfloat162float(h23.x));
        l23.y = __float2bfloat16_rn(v.w - __bfloat162float(h23.y));
        uint2 hu, lu;
        hu.x = *(uint32_t*)&h01; hu.y = *(uint32_t*)&h23;
        lu.x = *(uint32_t*)&l01; lu.y = *(uint32_t*)&l23;
        ((uint2*)hi)[off4] = hu;
        ((uint2*)lo)[off4] = lu;
    }
}

// ---------------------------------------------------------------------------
// Kernel 2: WMMA bf16 split GEMM  xg = inputs @ W_ih^T + (b_ih + b_hh)
// (unchanged — works)
// ---------------------------------------------------------------------------
#define GBM 128
#define GBN 128
#define GKC 64
#define LDA 72
#define LDC 132
#define SM_GEMM_BYTES (4 * 128 * LDA * 2)

__global__ __launch_bounds__(256) void xg_gemm_mma(
    const float* __restrict__ b_ih, const float* __restrict__ b_hh)
{
    extern __shared__ char smem[];
    __nv_bfloat16* A_hi = (__nv_bfloat16*)smem;
    __nv_bfloat16* A_lo = A_hi + 128 * LDA;
    __nv_bfloat16* B_hi = A_lo + 128 * LDA;
    __nv_bfloat16* B_lo = B_hi + 128 * LDA;

    const int tid = threadIdx.x;
    const int wid = tid >> 5;
    const int m0 = blockIdx.y * GBM;
    const int n0 = blockIdx.x * GBN;
    const int wm = wid >> 1;
    const int wn = wid & 1;

    wmma::fragment<wmma::accumulator, 16, 16, 16, float> C[2][4];
#pragma unroll
    for (int i = 0; i < 2; i++)
#pragma unroll
        for (int j = 0; j < 4; j++) wmma::fill_fragment(C[i][j], 0.0f);

    for (int kc = 0; kc < Dsz / GKC; kc++) {
        const int k0 = kc * GKC;
#pragma unroll
        for (int u = 0; u < 4; u++) {
            int unit = u * 256 + tid;
            int row = unit >> 3, c8 = unit & 7;
            size_t ga = (size_t)(m0 + row) * Dsz + k0 + c8 * 8;
            size_t gb = (size_t)(n0 + row) * Dsz + k0 + c8 * 8;
            int so = row * LDA + c8 * 8;
            *(uint4*)(A_hi + so) = *(const uint4*)(g_Ahi + ga);
            *(uint4*)(A_lo + so) = *(const uint4*)(g_Alo + ga);
            *(uint4*)(B_hi + so) = *(const uint4*)(g_Whi + gb);
            *(uint4*)(B_lo + so) = *(const uint4*)(g_Wlo + gb);
        }
        __syncthreads();

#pragma unroll
        for (int kk = 0; kk < GKC / 16; kk++) {
            wmma::fragment<wmma::matrix_a, 16, 16, 16, __nv_bfloat16, wmma::row_major> ah[2], al[2];
            wmma::fragment<wmma::matrix_b, 16, 16, 16, __nv_bfloat16, wmma::col_major> bh[4], bl[4];
#pragma unroll
            for (int i = 0; i < 2; i++) {
                int ro = (wm * 32 + i * 16) * LDA + kk * 16;
                wmma::load_matrix_sync(ah[i], A_hi + ro, LDA);
                wmma::load_matrix_sync(al[i], A_lo + ro, LDA);
            }
#pragma unroll
            for (int j = 0; j < 4; j++) {
                int ro = (wn * 64 + j * 16) * LDA + kk * 16;
                wmma::load_matrix_sync(bh[j], B_hi + ro, LDA);
                wmma::load_matrix_sync(bl[j], B_lo + ro, LDA);
            }
#pragma unroll
            for (int i = 0; i < 2; i++)
#pragma unroll
                for (int j = 0; j < 4; j++) {
                    wmma::mma_sync(C[i][j], ah[i], bh[j], C[i][j]);
                    wmma::mma_sync(C[i][j], ah[i], bl[j], C[i][j]);
                    wmma::mma_sync(C[i][j], al[i], bh[j], C[i][j]);
                }
        }
        __syncthreads();
    }

    float* Cs = (float*)smem;
#pragma unroll
    for (int i = 0; i < 2; i++)
#pragma unroll
        for (int j = 0; j < 4; j++)
            wmma::store_matrix_sync(Cs + (wm * 32 + i * 16) * LDC + wn * 64 + j * 16,
                                    C[i][j], LDC, wmma::mem_row_major);
    __syncthreads();

    {
        const int r    = tid >> 1;
        const int half = tid & 1;
        const int m = m0 + r;
        const int s = m & 511, b = m >> 9;
        float* orow = g_xg + ((size_t)s * Bn + b) * Gsz;
        const float* crow = Cs + r * LDC + half * 64;
#pragma unroll
        for (int q = 0; q < 16; q++) {
            int n = n0 + half * 64 + q * 4;
            float4 v  = *(const float4*)(crow + q * 4);
            float4 b1 = *(const float4*)(b_ih + n);
            float4 b2 = *(const float4*)(b_hh + n);
            v.x += b1.x + b2.x; v.y += b1.y + b2.y;
            v.z += b1.z + b2.z; v.w += b1.w + b2.w;
            *(float4*)(orow + n) = v;
        }
    }
}

// ---------------------------------------------------------------------------
// Kernel 3: persistent recurrent LSTM. 512 threads, 128 blocks =
// 4 b-columns x 32 j-slices; block = 16 j x 16 b (64 gate rows).
// NEW: W_hh fragments are REGISTER-RESIDENT (16 warps = 4 row-tiles x 4
// K-blocks; 64 regs of W per thread, loaded once via a temp smem stage).
// Per-step smem reads drop from 256KB to ~128KB (B-frags only).
// xg is software-pipelined one step ahead. Barrier: one release-arrival
// per block + acquire poll (round-8 scheme).
// ---------------------------------------------------------------------------
#define LDH  24                 // h smem ld (bf16)
#define LDCS 20                 // C partial ld (fp32)
#define LDWS 520                // W staging ld (init only)
#define OFF_H_HI 0
#define OFF_H_LO (Hsz * LDH * 2)                 // bytes
#define OFF_CS   (2 * Hsz * LDH * 2)             // bytes
#define REC_SMEM_BYTES (OFF_CS + 4 * 64 * LDCS * 4)   // 69632; > 64*520*2=66560 init

__global__ __launch_bounds__(512, 1) void lstm_rec_tc5(
    const float* __restrict__ h_n, const float* __restrict__ c_n,
    const float* __restrict__ W_hh, float* __restrict__ out)
{
    extern __shared__ char smem[];
    __nv_bfloat16* Hhi_s  = (__nv_bfloat16*)(smem + OFF_H_HI);  // [512][LDH]
    __nv_bfloat16* Hlo_s  = (__nv_bfloat16*)(smem + OFF_H_LO);
    float*         Cs     = (float*)(smem + OFF_CS);            // [4][64][LDCS]
    __nv_bfloat16* Wstage = (__nv_bfloat16*)smem;               // init only [64][LDWS]

    const int tid = threadIdx.x;
    const int wid = tid >> 5;
    const int bs  = blockIdx.x & 3;        // b-column
    const int js  = blockIdx.x >> 2;       // j-slice
    unsigned* cnt = &g_cnt[bs * 32];

    // mma identity: warp -> (row-tile, K-block)
    const int rt = wid & 3;                // rows rt*16..+15
    const int kh = wid >> 2;               // k kh*128..+127

    // ---- init: load W fragments into registers (hi pass, lo pass) ----
    wmma::fragment<wmma::matrix_a, 16, 16, 16, __nv_bfloat16, wmma::row_major> wa_hi[8], wa_lo[8];
#pragma unroll
    for (int pass = 0; pass < 2; pass++) {
        for (int idx = tid; idx < 64 * Hsz; idx += 512) {
            int r = idx >> 9, k = idx & 511;
            float w = W_hh[((size_t)(r >> 4) * Hsz + js * JT + (r & 15)) * Hsz + k];
            __nv_bfloat16 hi = __float2bfloat16_rn(w);
            Wstage[r * LDWS + k] = (pass == 0)
                ? hi : __float2bfloat16_rn(w - __bfloat162float(hi));
        }
        __syncthreads();
        if (pass == 0) {
#pragma unroll
            for (int kk = 0; kk < 8; kk++)
                wmma::load_matrix_sync(wa_hi[kk],
                    Wstage + (rt * 16) * LDWS + kh * 128 + kk * 16, LDWS);
        } else {
#pragma unroll
            for (int kk = 0; kk < 8; kk++)
                wmma::load_matrix_sync(wa_lo[kk],
                    Wstage + (rt * 16) * LDWS + kh * 128 + kk * 16, LDWS);
        }
        __syncthreads();
    }

    // cell identity (threads 0..255): tid = bb*16 + jj
    const int jj = tid & 15;
    const int bb = (tid >> 4) & 15;
    const bool is_cell = (tid < 256);
    const int j  = js * JT + jj;
    const int b  = bs * BT + bb;
    float c_reg = 0.f;
    if (is_cell) {
        c_reg = c_n[b * Hsz + j];
        float h0 = h_n[b * Hsz + j];
        __nv_bfloat16 hi = __float2bfloat16_rn(h0);
        __nv_bfloat16 lo = __float2bfloat16_rn(h0 - __bfloat162float(hi));
        __stcg((unsigned short*)&g_hsl[0][bs][0][j * BT + bb], __bfloat16_as_ushort(hi));
        __stcg((unsigned short*)&g_hsl[0][bs][1][j * BT + bb], __bfloat16_as_ushort(lo));
    }
    __syncthreads();                       // h[0] stores done (cta scope)

    unsigned target = NJ;                  // one arrival per block
    if (tid == 0) {
        red_release(cnt);
        while (ld_acquire(cnt) < target) { }
    }
    __syncthreads();

    // prefetch xg[0]
    float xi = 0.f, xf = 0.f, xg = 0.f, xo = 0.f;
    if (is_cell) {
        const float* xgp = g_xg + ((size_t)0 * Bn + b) * Gsz + j;
        xi = __ldcg(xgp + 0 * Hsz);
        xf = __ldcg(xgp + 1 * Hsz);
        xg = __ldcg(xgp + 2 * Hsz);
        xo = __ldcg(xgp + 3 * Hsz);
    }

    for (int t = 0; t < Ssz; t++) {
        // stage h slab (this b-column): 2048 uint4, 4 per thread
        {
            const uint4* shi = (const uint4*)g_hsl[t & 1][bs][0];
            const uint4* slo = (const uint4*)g_hsl[t & 1][bs][1];
#pragma unroll
            for (int it = 0; it < 2; it++) {
                int i = it * 512 + tid;       // 0..1023
                int j2 = i >> 1, half = i & 1;
                *(uint4*)(Hhi_s + j2 * LDH + half * 8) = __ldcg(shi + i);
                *(uint4*)(Hlo_s + j2 * LDH + half * 8) = __ldcg(slo + i);
            }
        }

        // software-pipeline xg[t+1] (latency hidden by mma below)
        float nxi = 0.f, nxf = 0.f, nxg = 0.f, nxo = 0.f;
        if (is_cell && t + 1 < Ssz) {
            const float* xgp = g_xg + ((size_t)(t + 1) * Bn + b) * Gsz + j;
            nxi = __ldcg(xgp + 0 * Hsz);
            nxf = __ldcg(xgp + 1 * Hsz);
            nxg = __ldcg(xgp + 2 * Hsz);
            nxo = __ldcg(xgp + 3 * Hsz);
        }
        __syncthreads();

        // warp mma: C(16 rows x 16 b) over K=128, W frags from registers
        {
            wmma::fragment<wmma::accumulator, 16, 16, 16, float> chh, cx;
            wmma::fill_fragment(chh, 0.0f);
            wmma::fill_fragment(cx, 0.0f);
#pragma unroll
            for (int kk = 0; kk < 8; kk++) {
                int k = kh * 128 + kk * 16;
                wmma::fragment<wmma::matrix_b, 16, 16, 16, __nv_bfloat16, wmma::row_major> bh, bl;
                wmma::load_matrix_sync(bh, Hhi_s + k * LDH, LDH);
                wmma::load_matrix_sync(bl, Hlo_s + k * LDH, LDH);
                wmma::mma_sync(chh, wa_hi[kk], bh, chh);
                wmma::mma_sync(cx,  wa_hi[kk], bl, cx);
                wmma::mma_sync(cx,  wa_lo[kk], bh, cx);
            }
#pragma unroll
            for (int i = 0; i < chh.num_elements; i++)
                chh.x[i] += cx.x[i];
            wmma::store_matrix_sync(Cs + (kh * 64 + rt * 16) * LDCS, chh, LDCS,
                                    wmma::mem_row_major);
        }
        __syncthreads();

        // elementwise LSTM cell; reduce 4 K-blocks
        if (is_cell) {
            float gi = xi, gf = xf, gg = xg, go = xo;
#pragma unroll
            for (int q = 0; q < 4; q++) {
                const float* Cq = Cs + q * 64 * LDCS;
                gi += Cq[(0  + jj) * LDCS + bb];
                gf += Cq[(16 + jj) * LDCS + bb];
                gg += Cq[(32 + jj) * LDCS + bb];
                go += Cq[(48 + jj) * LDCS + bb];
            }
            float si = 1.f / (1.f + __expf(-gi));
            float sf = 1.f / (1.f + __expf(-gf));
            float so = 1.f / (1.f + __expf(-go));
            float tg = tanhf(gg);
            c_reg = sf * c_reg + si * tg;
            float hnew = so * tanhf(c_reg);

            __nv_bfloat16 hi = __float2bfloat16_rn(hnew);
            __nv_bfloat16 lo = __float2bfloat16_rn(hnew - __bfloat162float(hi));
            int pp = (t + 1) & 1;
            __stcg((unsigned short*)&g_hsl[pp][bs][0][j * BT + bb], __bfloat16_as_ushort(hi));
            __stcg((unsigned short*)&g_hsl[pp][bs][1][j * BT + bb], __bfloat16_as_ushort(lo));

            __stcg(&out[((size_t)b * Ssz + t) * Hsz + j], hnew);

            xi = nxi; xf = nxf; xg = nxg; xo = nxo;
        }
        __syncthreads();                   // publish stores happen-before arrival

        target += NJ;
        if (tid == 0) {
            red_release(cnt);              // release covers bar-synced stcg stores
            while (ld_acquire(cnt) < target) { }
        }
        __syncthreads();
    }

    // self-reset counters for next graph replay (last block chip-wide)
    if (tid == 0) {
        if (atomicAdd(&g_done, 1u) == NBS * NJ - 1) {
            for (int i = 0; i < NBS; i++) g_cnt[i * 32] = 0u;
            g_done = 0u;
            __threadfence();
        }
    }
}

// ---------------------------------------------------------------------------
// kernel_launch
// inputs: 0:x 1:emb 2:h_n 3:c_n 4:W_ih 5:W_hh 6:b_ih 7:b_hh
// ---------------------------------------------------------------------------
extern "C" void kernel_launch(void* const* d_in, const int* in_sizes, int n_in,
                              void* d_out, int out_size)
{
    const float* x    = (const float*)d_in[0];
    const float* emb  = (const float*)d_in[1];
    const float* h_n  = (const float*)d_in[2];
    const float* c_n  = (const float*)d_in[3];
    const float* W_ih = (const float*)d_in[4];
    const float* W_hh = (const float*)d_in[5];
    const float* b_ih = (const float*)d_in[6];
    const float* b_hh = (const float*)d_in[7];
    float* out = (float*)d_out;

    cudaFuncSetAttribute(xg_gemm_mma, cudaFuncAttributeMaxDynamicSharedMemorySize,
                         SM_GEMM_BYTES);
    cudaFuncSetAttribute(lstm_rec_tc5, cudaFuncAttributeMaxDynamicSharedMemorySize,
                         REC_SMEM_BYTES);

    convert_kernel<<<1024, 256>>>(x, emb, W_ih);
    xg_gemm_mma<<<dim3(Gsz / GBN, (Bn * Ssz) / GBM), 256, SM_GEMM_BYTES>>>(b_ih, b_hh);
    lstm_rec_tc5<<<NBS * NJ, 512, REC_SMEM_BYTES>>>(h_n, c_n, W_hh, out);
}

// round 10
// speedup vs baseline: 2.9162x; 1.0087x over previous
#include <cuda_runtime.h>
#include <cuda_bf16.h>
#include <mma.h>
#include <cstdint>

using namespace nvcuda;

#define Bn  64
#define Ssz 512
#define Dsz 512
#define Hsz 512
#define Gsz 2048   // 4*H

// recurrent tiling: 4 b-columns x 32 j-slices = 128 blocks, 256 threads each
#define NBS 4      // b-slices
#define NJ  32     // j-slice blocks per b-column
#define JT  16     // j per block
#define BT  16     // b per block

// ---------------------------------------------------------------------------
// global scratch
// ---------------------------------------------------------------------------
__device__ float         g_xg[(size_t)Ssz * Bn * Gsz];       // 256 MB
__device__ __nv_bfloat16 g_hsl[2][NBS][2][Hsz * BT];         // [ping][bs][hi/lo][j*16+bb]
__device__ unsigned      g_cnt[NBS * 32];                    // 128B-spaced counters
__device__ unsigned      g_done;
__device__ __nv_bfloat16 g_Ahi[(size_t)Bn * Ssz * Dsz];      // inputs hi
__device__ __nv_bfloat16 g_Alo[(size_t)Bn * Ssz * Dsz];      // inputs lo
__device__ __nv_bfloat16 g_Whi[(size_t)Gsz * Dsz];           // W_ih hi
__device__ __nv_bfloat16 g_Wlo[(size_t)Gsz * Dsz];           // W_ih lo

// ---------------------------------------------------------------------------
// light device-scope sync primitives (no membar.gl -> no L1 flush)
// ---------------------------------------------------------------------------
__device__ __forceinline__ void red_release(unsigned* p) {
    asm volatile("red.release.gpu.global.add.u32 [%0], 1;" :: "l"(p) : "memory");
}
__device__ __forceinline__ unsigned ld_acquire(unsigned* p) {
    unsigned v;
    asm volatile("ld.acquire.gpu.global.u32 %0, [%1];" : "=r"(v) : "l"(p) : "memory");
    return v;
}
// precise-enough tanh: 1 - 2/(e^{2x}+1); ~1e-6 rel err, 2 MUFU ops
__device__ __forceinline__ float tanh_cheap(float x) {
    return 1.0f - __fdividef(2.0f, __expf(2.0f * x) + 1.0f);
}

// ---------------------------------------------------------------------------
// Kernel 1: fp32 -> (hi,lo) bf16 split for inputs (with emb shift) and W_ih
// ---------------------------------------------------------------------------
__global__ __launch_bounds__(256) void convert_kernel(
    const float* __restrict__ x, const float* __restrict__ emb,
    const float* __restrict__ W_ih)
{
    const int A4 = (Bn * Ssz * Dsz) / 4;
    const int T4 = A4 + (Gsz * Dsz) / 4;
    for (int idx = blockIdx.x * 256 + threadIdx.x; idx < T4; idx += gridDim.x * 256) {
        const float* src;
        __nv_bfloat16 *hi, *lo;
        int off4;
        if (idx < A4) {
            int m = idx >> 7, c = idx & 127;
            int s = m & 511;
            src = (s == 0) ? (emb + (size_t)(m >> 9) * Dsz)
                           : (x + (size_t)(m - 1) * Dsz);
            src += c * 4;
            hi = g_Ahi; lo = g_Alo; off4 = idx;
        } else {
            int i2 = idx - A4;
            src = W_ih + (size_t)i2 * 4;
            hi = g_Whi; lo = g_Wlo; off4 = i2;
        }
        float4 v = *(const float4*)src;
        __nv_bfloat162 h01, h23, l01, l23;
        h01.x = __float2bfloat16_rn(v.x); h01.y = __float2bfloat16_rn(v.y);
        h23.x = __float2bfloat16_rn(v.z); h23.y = __float2bfloat16_rn(v.w);
        l01.x = __float2bfloat16_rn(v.x - __bfloat162float(h01.x));
        l01.y = __float2bfloat16_rn(v.y - __bfloat162float(h01.y));
        l23.x = __float2bfloat16_rn(v.z - __bfloat162float(h23.x));
        l23.y = __float2bfloat16_rn(v.w - __bfloat162float(h23.y));
        uint2 hu, lu;
        hu.x = *(uint32_t*)&h01; hu.y = *(uint32_t*)&h23;
        lu.x = *(uint32_t*)&l01; lu.y = *(uint32_t*)&l23;
        ((uint2*)hi)[off4] = hu;
        ((uint2*)lo)[off4] = lu;
    }
}

// ---------------------------------------------------------------------------
// Kernel 2: WMMA bf16 split GEMM  xg = inputs @ W_ih^T + (b_ih + b_hh)
// (unchanged — works)
// ---------------------------------------------------------------------------
#define GBM 128
#define GBN 128
#define GKC 64
#define LDA 72
#define LDC 132
#define SM_GEMM_BYTES (4 * 128 * LDA * 2)

__global__ __launch_bounds__(256) void xg_gemm_mma(
    const float* __restrict__ b_ih, const float* __restrict__ b_hh)
{
    extern __shared__ char smem[];
    __nv_bfloat16* A_hi = (__nv_bfloat16*)smem;
    __nv_bfloat16* A_lo = A_hi + 128 * LDA;
    __nv_bfloat16* B_hi = A_lo + 128 * LDA;
    __nv_bfloat16* B_lo = B_hi + 128 * LDA;

    const int tid = threadIdx.x;
    const int wid = tid >> 5;
    const int m0 = blockIdx.y * GBM;
    const int n0 = blockIdx.x * GBN;
    const int wm = wid >> 1;
    const int wn = wid & 1;

    wmma::fragment<wmma::accumulator, 16, 16, 16, float> C[2][4];
#pragma unroll
    for (int i = 0; i < 2; i++)
#pragma unroll
        for (int j = 0; j < 4; j++) wmma::fill_fragment(C[i][j], 0.0f);

    for (int kc = 0; kc < Dsz / GKC; kc++) {
        const int k0 = kc * GKC;
#pragma unroll
        for (int u = 0; u < 4; u++) {
            int unit = u * 256 + tid;
            int row = unit >> 3, c8 = unit & 7;
            size_t ga = (size_t)(m0 + row) * Dsz + k0 + c8 * 8;
            size_t gb = (size_t)(n0 + row) * Dsz + k0 + c8 * 8;
            int so = row * LDA + c8 * 8;
            *(uint4*)(A_hi + so) = *(const uint4*)(g_Ahi + ga);
            *(uint4*)(A_lo + so) = *(const uint4*)(g_Alo + ga);
            *(uint4*)(B_hi + so) = *(const uint4*)(g_Whi + gb);
            *(uint4*)(B_lo + so) = *(const uint4*)(g_Wlo + gb);
        }
        __syncthreads();

#pragma unroll
        for (int kk = 0; kk < GKC / 16; kk++) {
            wmma::fragment<wmma::matrix_a, 16, 16, 16, __nv_bfloat16, wmma::row_major> ah[2], al[2];
            wmma::fragment<wmma::matrix_b, 16, 16, 16, __nv_bfloat16, wmma::col_major> bh[4], bl[4];
#pragma unroll
            for (int i = 0; i < 2; i++) {
                int ro = (wm * 32 + i * 16) * LDA + kk * 16;
                wmma::load_matrix_sync(ah[i], A_hi + ro, LDA);
                wmma::load_matrix_sync(al[i], A_lo + ro, LDA);
            }
#pragma unroll
            for (int j = 0; j < 4; j++) {
                int ro = (wn * 64 + j * 16) * LDA + kk * 16;
                wmma::load_matrix_sync(bh[j], B_hi + ro, LDA);
                wmma::load_matrix_sync(bl[j], B_lo + ro, LDA);
            }
#pragma unroll
            for (int i = 0; i < 2; i++)
#pragma unroll
                for (int j = 0; j < 4; j++) {
                    wmma::mma_sync(C[i][j], ah[i], bh[j], C[i][j]);
                    wmma::mma_sync(C[i][j], ah[i], bl[j], C[i][j]);
                    wmma::mma_sync(C[i][j], al[i], bh[j], C[i][j]);
                }
        }
        __syncthreads();
    }

    float* Cs = (float*)smem;
#pragma unroll
    for (int i = 0; i < 2; i++)
#pragma unroll
        for (int j = 0; j < 4; j++)
            wmma::store_matrix_sync(Cs + (wm * 32 + i * 16) * LDC + wn * 64 + j * 16,
                                    C[i][j], LDC, wmma::mem_row_major);
    __syncthreads();

    {
        const int r    = tid >> 1;
        const int half = tid & 1;
        const int m = m0 + r;
        const int s = m & 511, b = m >> 9;
        float* orow = g_xg + ((size_t)s * Bn + b) * Gsz;
        const float* crow = Cs + r * LDC + half * 64;
#pragma unroll
        for (int q = 0; q < 16; q++) {
            int n = n0 + half * 64 + q * 4;
            float4 v  = *(const float4*)(crow + q * 4);
            float4 b1 = *(const float4*)(b_ih + n);
            float4 b2 = *(const float4*)(b_hh + n);
            v.x += b1.x + b2.x; v.y += b1.y + b2.y;
            v.z += b1.z + b2.z; v.w += b1.w + b2.w;
            *(float4*)(orow + n) = v;
        }
    }
}

// ---------------------------------------------------------------------------
// Kernel 3: persistent recurrent LSTM. 256 threads (8 warps), 128 blocks =
// 4 b-columns x 32 j-slices; block = 16 j x 16 b (64 gate rows).
// Warp = (row-half of 32 rows) x (K-block of 128). Whi frags REGISTER-
// RESIDENT (16 frags = 128 regs; 256-reg budget at 256 thr — NO SPILLS).
// Wlo permanent in smem (re-read per step). xg software-pipelined.
// Barrier: one release-arrival per block + acquire poll.
// ---------------------------------------------------------------------------
#define LDH  24                 // h smem ld (bf16)
#define LDCS 20                 // C partial ld (fp32)
#define LDWS 520                // W smem ld (bf16)
#define OFF_WLO  0                                      // bytes; permanent 66560
#define OFF_HHI  66560
#define OFF_HLO  (66560 + Hsz * LDH * 2)                // 91136
#define OFF_CS   (66560 + 2 * Hsz * LDH * 2)            // 115712
#define REC_SMEM_BYTES (OFF_CS + 4 * 64 * LDCS * 4)     // 136192

__global__ __launch_bounds__(256, 1) void lstm_rec_tc6(
    const float* __restrict__ h_n, const float* __restrict__ c_n,
    const float* __restrict__ W_hh, float* __restrict__ out)
{
    extern __shared__ char smem[];
    __nv_bfloat16* Wlo_s  = (__nv_bfloat16*)(smem + OFF_WLO);   // [64][LDWS] permanent
    __nv_bfloat16* Hhi_s  = (__nv_bfloat16*)(smem + OFF_HHI);   // [512][LDH]
    __nv_bfloat16* Hlo_s  = (__nv_bfloat16*)(smem + OFF_HLO);
    float*         Cs     = (float*)(smem + OFF_CS);            // [4][64][LDCS]
    __nv_bfloat16* WhiStg = (__nv_bfloat16*)(smem + OFF_HHI);   // init-only overlay

    const int tid = threadIdx.x;
    const int wid = tid >> 5;
    const int bs  = blockIdx.x & 3;        // b-column
    const int js  = blockIdx.x >> 2;       // j-slice
    unsigned* cnt = &g_cnt[bs * 32];

    // mma identity: warp -> (row-half, K-block)
    const int rt = wid & 1;                // rows rt*32 .. +31
    const int kh = wid >> 1;               // k kh*128 .. +127

    // ---- init: Wlo -> permanent smem, Whi -> staging, then frags -> regs ----
    for (int idx = tid; idx < 64 * Hsz; idx += 256) {
        int r = idx >> 9, k = idx & 511;
        float w = W_hh[((size_t)(r >> 4) * Hsz + js * JT + (r & 15)) * Hsz + k];
        __nv_bfloat16 hi = __float2bfloat16_rn(w);
        WhiStg[r * LDWS + k] = hi;
        Wlo_s [r * LDWS + k] = __float2bfloat16_rn(w - __bfloat162float(hi));
    }
    __syncthreads();

    wmma::fragment<wmma::matrix_a, 16, 16, 16, __nv_bfloat16, wmma::row_major> wa_hi[2][8];
#pragma unroll
    for (int mi = 0; mi < 2; mi++)
#pragma unroll
        for (int kk = 0; kk < 8; kk++)
            wmma::load_matrix_sync(wa_hi[mi][kk],
                WhiStg + (rt * 32 + mi * 16) * LDWS + kh * 128 + kk * 16, LDWS);
    __syncthreads();                       // done with Whi staging overlay

    // cell identity: tid = bb*16 + jj  (all 256 threads are cell threads)
    const int jj = tid & 15;
    const int bb = tid >> 4;
    const int j  = js * JT + jj;
    const int b  = bs * BT + bb;
    float c_reg = c_n[b * Hsz + j];
    {
        float h0 = h_n[b * Hsz + j];
        __nv_bfloat16 hi = __float2bfloat16_rn(h0);
        __nv_bfloat16 lo = __float2bfloat16_rn(h0 - __bfloat162float(hi));
        __stcg((unsigned short*)&g_hsl[0][bs][0][j * BT + bb], __bfloat16_as_ushort(hi));
        __stcg((unsigned short*)&g_hsl[0][bs][1][j * BT + bb], __bfloat16_as_ushort(lo));
    }
    __syncthreads();                       // h[0] stores done (cta scope)

    unsigned target = NJ;                  // one arrival per block
    if (tid == 0) {
        red_release(cnt);
        while (ld_acquire(cnt) < target) { }
    }
    __syncthreads();

    // prefetch xg[0]
    const float* xgp0 = g_xg + (size_t)b * Gsz + j;
    float xi = __ldcg(xgp0 + 0 * Hsz);
    float xf = __ldcg(xgp0 + 1 * Hsz);
    float xg = __ldcg(xgp0 + 2 * Hsz);
    float xo = __ldcg(xgp0 + 3 * Hsz);

    for (int t = 0; t < Ssz; t++) {
        // stage h slab (this b-column): 1024 uint4 per plane, 4+4 per thread
        {
            const uint4* shi = (const uint4*)g_hsl[t & 1][bs][0];
            const uint4* slo = (const uint4*)g_hsl[t & 1][bs][1];
#pragma unroll
            for (int it = 0; it < 4; it++) {
                int i = it * 256 + tid;       // 0..1023
                int j2 = i >> 1, half = i & 1;
                *(uint4*)(Hhi_s + j2 * LDH + half * 8) = __ldcg(shi + i);
                *(uint4*)(Hlo_s + j2 * LDH + half * 8) = __ldcg(slo + i);
            }
        }

        // software-pipeline xg[t+1]
        float nxi = 0.f, nxf = 0.f, nxg = 0.f, nxo = 0.f;
        if (t + 1 < Ssz) {
            const float* xgp = g_xg + ((size_t)(t + 1) * Bn + b) * Gsz + j;
            nxi = __ldcg(xgp + 0 * Hsz);
            nxf = __ldcg(xgp + 1 * Hsz);
            nxg = __ldcg(xgp + 2 * Hsz);
            nxo = __ldcg(xgp + 3 * Hsz);
        }
        __syncthreads();

        // warp mma: 32 rows x 16 b over K=128; Whi from registers
        {
            wmma::fragment<wmma::accumulator, 16, 16, 16, float> chh[2], cx[2];
#pragma unroll
            for (int mi = 0; mi < 2; mi++) {
                wmma::fill_fragment(chh[mi], 0.0f);
                wmma::fill_fragment(cx[mi], 0.0f);
            }
#pragma unroll
            for (int kk = 0; kk < 8; kk++) {
                int k = kh * 128 + kk * 16;
                wmma::fragment<wmma::matrix_b, 16, 16, 16, __nv_bfloat16, wmma::row_major> bh, bl;
                wmma::load_matrix_sync(bh, Hhi_s + k * LDH, LDH);
                wmma::load_matrix_sync(bl, Hlo_s + k * LDH, LDH);
#pragma unroll
                for (int mi = 0; mi < 2; mi++) {
                    wmma::fragment<wmma::matrix_a, 16, 16, 16, __nv_bfloat16, wmma::row_major> wl;
                    wmma::load_matrix_sync(wl,
                        Wlo_s + (rt * 32 + mi * 16) * LDWS + k, LDWS);
                    wmma::mma_sync(chh[mi], wa_hi[mi][kk], bh, chh[mi]);
                    wmma::mma_sync(cx[mi],  wa_hi[mi][kk], bl, cx[mi]);
                    wmma::mma_sync(cx[mi],  wl, bh, cx[mi]);
                }
            }
#pragma unroll
            for (int mi = 0; mi < 2; mi++) {
#pragma unroll
                for (int i = 0; i < chh[mi].num_elements; i++)
                    chh[mi].x[i] += cx[mi].x[i];
                wmma::store_matrix_sync(
                    Cs + (kh * 64 + rt * 32 + mi * 16) * LDCS, chh[mi], LDCS,
                    wmma::mem_row_major);
            }
        }
        __syncthreads();

        // elementwise LSTM cell; reduce 4 K-blocks
        {
            float gi = xi, gf = xf, gg = xg, go = xo;
#pragma unroll
            for (int q = 0; q < 4; q++) {
                const float* Cq = Cs + q * 64 * LDCS;
                gi += Cq[(0  + jj) * LDCS + bb];
                gf += Cq[(16 + jj) * LDCS + bb];
                gg += Cq[(32 + jj) * LDCS + bb];
                go += Cq[(48 + jj) * LDCS + bb];
            }
            float si = 1.f / (1.f + __expf(-gi));
            float sf = 1.f / (1.f + __expf(-gf));
            float so = 1.f / (1.f + __expf(-go));
            float tg = tanh_cheap(gg);
            c_reg = sf * c_reg + si * tg;
            float hnew = so * tanh_cheap(c_reg);

            __nv_bfloat16 hi = __float2bfloat16_rn(hnew);
            __nv_bfloat16 lo = __float2bfloat16_rn(hnew - __bfloat162float(hi));
            int pp = (t + 1) & 1;
            __stcg((unsigned short*)&g_hsl[pp][bs][0][j * BT + bb], __bfloat16_as_ushort(hi));
            __stcg((unsigned short*)&g_hsl[pp][bs][1][j * BT + bb], __bfloat16_as_ushort(lo));

            __stcg(&out[((size_t)b * Ssz + t) * Hsz + j], hnew);

            xi = nxi; xf = nxf; xg = nxg; xo = nxo;
        }
        __syncthreads();                   // publish stores happen-before arrival

        target += NJ;
        if (tid == 0) {
            red_release(cnt);              // release covers bar-synced stcg stores
            while (ld_acquire(cnt) < target) { }
        }
        __syncthreads();
    }

    // self-reset counters for next graph replay (last block chip-wide)
    if (tid == 0) {
        if (atomicAdd(&g_done, 1u) == NBS * NJ - 1) {
            for (int i = 0; i < NBS; i++) g_cnt[i * 32] = 0u;
            g_done = 0u;
            __threadfence();
        }
    }
}

// ---------------------------------------------------------------------------
// kernel_launch
// inputs: 0:x 1:emb 2:h_n 3:c_n 4:W_ih 5:W_hh 6:b_ih 7:b_hh
// ---------------------------------------------------------------------------
extern "C" void kernel_launch(void* const* d_in, const int* in_sizes, int n_in,
                              void* d_out, int out_size)
{
    const float* x    = (const float*)d_in[0];
    const float* emb  = (const float*)d_in[1];
    const float* h_n  = (const float*)d_in[2];
    const float* c_n  = (const float*)d_in[3];
    const float* W_ih = (const float*)d_in[4];
    const float* W_hh = (const float*)d_in[5];
    const float* b_ih = (const float*)d_in[6];
    const float* b_hh = (const float*)d_in[7];
    float* out = (float*)d_out;

    cudaFuncSetAttribute(xg_gemm_mma, cudaFuncAttributeMaxDynamicSharedMemorySize,
                         SM_GEMM_BYTES);
    cudaFuncSetAttribute(lstm_rec_tc6, cudaFuncAttributeMaxDynamicSharedMemorySize,
                         REC_SMEM_BYTES);

    convert_kernel<<<1024, 256>>>(x, emb, W_ih);
    xg_gemm_mma<<<dim3(Gsz / GBN, (Bn * Ssz) / GBM), 256, SM_GEMM_BYTES>>>(b_ih, b_hh);
    lstm_rec_tc6<<<NBS * NJ, 256, REC_SMEM_BYTES>>>(h_n, c_n, W_hh, out);
}